// round 11
// baseline (speedup 1.0000x reference)
#include <cuda_runtime.h>
#include <math.h>
#include <stdint.h>

static constexpr int B = 4, N = 2048, DIM = 768, H = 12, DH = 64, MLP = 3072, L = 2;
static constexpr int M = B * N;            // 8192 rows
static constexpr int HD = H * DH;          // 768

// ---------------- scratch (device globals; no allocation allowed) -------------
__device__ float g_x   [M * DIM];
__device__ float g_xn  [M * DIM];
__device__ float g_qlin[M * HD];
__device__ float g_kv  [M * 2 * HD];
__device__ float g_Q   [B * H * N * DH];
__device__ float g_K   [B * H * N * DH];
__device__ float g_V   [B * H * N * DH];
__device__ float g_att [M * HD];
__device__ float g_h   [M * MLP];

// ---------------- tf32 / async helpers ---------------------------------------
__device__ __forceinline__ unsigned f2tf(float f) {
    unsigned u; asm("cvt.rna.tf32.f32 %0, %1;" : "=r"(u) : "f"(f)); return u;
}

__device__ __forceinline__ void mma_tf32(float* c, const unsigned* a, unsigned b0, unsigned b1) {
    asm volatile("mma.sync.aligned.m16n8k8.row.col.f32.tf32.tf32.f32 "
                 "{%0,%1,%2,%3}, {%4,%5,%6,%7}, {%8,%9}, {%0,%1,%2,%3};"
                 : "+f"(c[0]), "+f"(c[1]), "+f"(c[2]), "+f"(c[3])
                 : "r"(a[0]), "r"(a[1]), "r"(a[2]), "r"(a[3]), "r"(b0), "r"(b1));
}

__device__ __forceinline__ void cp16(float* smem_dst, const float* gsrc) {
    unsigned d = (unsigned)__cvta_generic_to_shared(smem_dst);
    asm volatile("cp.async.cg.shared.global [%0], [%1], 16;" :: "r"(d), "l"(gsrc));
}
__device__ __forceinline__ void cp_commit() { asm volatile("cp.async.commit_group;"); }
__device__ __forceinline__ void cp_wait1()  { asm volatile("cp.async.wait_group 1;"); }
__device__ __forceinline__ void cp_wait0()  { asm volatile("cp.async.wait_group 0;"); }

// ---------------- LayerNorm: one warp per row, DIM=768 -----------------------
__global__ void ln_kernel(const float* __restrict__ in, const float* __restrict__ g,
                          float* __restrict__ out)
{
    int warp = (blockIdx.x * blockDim.x + threadIdx.x) >> 5;
    int lane = threadIdx.x & 31;
    const float* x = in + (size_t)warp * DIM;
    float4 v[6];
    float s = 0.f;
#pragma unroll
    for (int i = 0; i < 6; i++) {
        v[i] = *(const float4*)(x + i * 128 + lane * 4);
        s += v[i].x + v[i].y + v[i].z + v[i].w;
    }
#pragma unroll
    for (int o = 16; o; o >>= 1) s += __shfl_xor_sync(0xffffffffu, s, o);
    float mean = s * (1.0f / DIM);
    float s2 = 0.f;
#pragma unroll
    for (int i = 0; i < 6; i++) {
        float a = v[i].x - mean, b = v[i].y - mean, c = v[i].z - mean, d = v[i].w - mean;
        s2 += a * a + b * b + c * c + d * d;
    }
#pragma unroll
    for (int o = 16; o; o >>= 1) s2 += __shfl_xor_sync(0xffffffffu, s2, o);
    float inv = rsqrtf(s2 * (1.0f / DIM) + 1e-5f);
    float* y = out + (size_t)warp * DIM;
#pragma unroll
    for (int i = 0; i < 6; i++) {
        float4 gg = *(const float4*)(g + i * 128 + lane * 4);
        float4 o4;
        o4.x = (v[i].x - mean) * inv * gg.x;
        o4.y = (v[i].y - mean) * inv * gg.y;
        o4.z = (v[i].z - mean) * inv * gg.z;
        o4.w = (v[i].w - mean) * inv * gg.w;
        *(float4*)(y + i * 128 + lane * 4) = o4;
    }
}

// ---------------- hybrid GEMM: tensor CTAs + FMA CTAs -------------------------
// C[M,Nc] = A[M,K]@W[K,Nc]; mode bit0:+bias, bit1:gelu, bit2:+res
// blockIdx.x <  nT : tensor path, 128-wide tile (tf32 mma, cp.async 2-stage)
// blockIdx.x >= nT : FMA path, 32-wide tile (exact fp32)
#define GBM 128
#define GBN 128
#define GBK 32
#define A_LD 36    // floats; 144B = 9*16
#define B_LD 136   // floats; 544B = 34*16
#define ASZ (GBM * A_LD)   // 4608 floats
#define BSZ (GBK * B_LD)   // 4352 floats
static const int GEMM_SMEM = 2 * (ASZ + BSZ) * 4;  // 71680 B

#define FA_LD 132  // fma A pad
#define FB_LD 36   // fma B pad

__device__ __forceinline__ float gelu_f(float v) {
    return 0.5f * v * (1.0f + erff(v * 0.70710678118654752f));
}

__global__ __launch_bounds__(256, 2)
void gemm_hyb(const float* __restrict__ A, const float* __restrict__ W,
              const float* __restrict__ bias, const float* __restrict__ res,
              float* __restrict__ C, int K_, int Nc, int mode, int nT)
{
    extern __shared__ float smg[];
    int t = threadIdx.x;
    int m0 = blockIdx.y * GBM;

    if ((int)blockIdx.x < nT) {
        // ---------------- tensor path (128-wide) ----------------
        float* Asm[2] = { smg, smg + ASZ };
        float* Bsm[2] = { smg + 2 * ASZ, smg + 2 * ASZ + BSZ };

        int warp = t >> 5, lane = t & 31;
        int group = lane >> 2, tid = lane & 3;
        int wm = warp >> 1, wn = warp & 1;
        int wr = wm * 32, wc = wn * 64;
        int n0 = blockIdx.x * GBN;

        int a_row = t >> 3, a_k4 = (t & 7) * 4;
        int b_kr = t >> 5, b_n4 = (t & 31) * 4;

        float acc[2][8][4];
#pragma unroll
        for (int a = 0; a < 2; a++)
#pragma unroll
            for (int b = 0; b < 8; b++)
#pragma unroll
                for (int c = 0; c < 4; c++) acc[a][b][c] = 0.f;

        int KT = K_ / GBK;
        {
            const float* Ab = A + (size_t)m0 * K_;
            const float* Bb = W + n0;
#pragma unroll
            for (int i = 0; i < 4; i++)
                cp16(&Asm[0][(a_row + i * 32) * A_LD + a_k4], Ab + (size_t)(a_row + i * 32) * K_ + a_k4);
#pragma unroll
            for (int i = 0; i < 4; i++)
                cp16(&Bsm[0][(b_kr + i * 8) * B_LD + b_n4], Bb + (size_t)(b_kr + i * 8) * Nc + b_n4);
            cp_commit();
        }

        for (int kt = 0; kt < KT; kt++) {
            cp_wait0();
            __syncthreads();
            if (kt + 1 < KT) {
                int s = (kt + 1) & 1;
                int k0 = (kt + 1) * GBK;
                const float* Ab = A + (size_t)m0 * K_ + k0;
                const float* Bb = W + (size_t)k0 * Nc + n0;
#pragma unroll
                for (int i = 0; i < 4; i++)
                    cp16(&Asm[s][(a_row + i * 32) * A_LD + a_k4], Ab + (size_t)(a_row + i * 32) * K_ + a_k4);
#pragma unroll
                for (int i = 0; i < 4; i++)
                    cp16(&Bsm[s][(b_kr + i * 8) * B_LD + b_n4], Bb + (size_t)(b_kr + i * 8) * Nc + b_n4);
                cp_commit();
            }
            const float* As = Asm[kt & 1];
            const float* Bs = Bsm[kt & 1];
#pragma unroll
            for (int kk = 0; kk < 4; kk++) {
                int k8 = kk * 8;
                unsigned a[2][4];
#pragma unroll
                for (int mt = 0; mt < 2; mt++) {
                    int r0 = wr + mt * 16;
                    a[mt][0] = f2tf(As[(r0 + group) * A_LD + k8 + tid]);
                    a[mt][1] = f2tf(As[(r0 + 8 + group) * A_LD + k8 + tid]);
                    a[mt][2] = f2tf(As[(r0 + group) * A_LD + k8 + tid + 4]);
                    a[mt][3] = f2tf(As[(r0 + 8 + group) * A_LD + k8 + tid + 4]);
                }
#pragma unroll
                for (int nt = 0; nt < 8; nt++) {
                    unsigned b0 = f2tf(Bs[(k8 + tid) * B_LD + wc + nt * 8 + group]);
                    unsigned b1 = f2tf(Bs[(k8 + tid + 4) * B_LD + wc + nt * 8 + group]);
                    mma_tf32(acc[0][nt], a[0], b0, b1);
                    mma_tf32(acc[1][nt], a[1], b0, b1);
                }
            }
        }

#pragma unroll
        for (int mt = 0; mt < 2; mt++) {
#pragma unroll
            for (int half = 0; half < 2; half++) {
                int r = m0 + wr + mt * 16 + half * 8 + group;
#pragma unroll
                for (int nt = 0; nt < 8; nt++) {
                    int c = n0 + wc + nt * 8 + tid * 2;
                    float v0 = acc[mt][nt][half * 2 + 0];
                    float v1 = acc[mt][nt][half * 2 + 1];
                    if (mode & 1) { v0 += bias[c]; v1 += bias[c + 1]; }
                    if (mode & 2) { v0 = gelu_f(v0); v1 = gelu_f(v1); }
                    if (mode & 4) {
                        float2 rr = *(const float2*)(res + (size_t)r * Nc + c);
                        v0 += rr.x; v1 += rr.y;
                    }
                    float2 o = { v0, v1 };
                    *(float2*)(C + (size_t)r * Nc + c) = o;
                }
            }
        }
    } else {
        // ---------------- FMA path (32-wide, exact fp32) ----------------
        float* As = smg;                 // [16][FA_LD]
        float* Bs = smg + 16 * FA_LD;    // [16][FB_LD]
        int fx = blockIdx.x - nT;
        int n0 = nT * GBN + fx * 32;
        int tx = t & 7, ty = t >> 3;     // 8 x 32 threads; 4 cols x 4 rows each

        float acc[4][4];
#pragma unroll
        for (int r = 0; r < 4; r++)
#pragma unroll
            for (int c = 0; c < 4; c++) acc[r][c] = 0.f;

        for (int k0 = 0; k0 < K_; k0 += 16) {
            __syncthreads();
#pragma unroll
            for (int i = 0; i < 8; i++) {
                int e = t + i * 256;
                int k = e & 15, mm = e >> 4;
                As[k * FA_LD + mm] = A[(size_t)(m0 + mm) * K_ + k0 + k];
            }
#pragma unroll
            for (int i = 0; i < 2; i++) {
                int e = t + i * 256;
                int nn = e & 31, k = e >> 5;
                Bs[k * FB_LD + nn] = W[(size_t)(k0 + k) * Nc + n0 + nn];
            }
            __syncthreads();
#pragma unroll
            for (int k = 0; k < 16; k++) {
                float4 a4 = *(const float4*)&As[k * FA_LD + ty * 4];
                float4 b4 = *(const float4*)&Bs[k * FB_LD + tx * 4];
                float av[4] = { a4.x, a4.y, a4.z, a4.w };
                float bv[4] = { b4.x, b4.y, b4.z, b4.w };
#pragma unroll
                for (int r = 0; r < 4; r++)
#pragma unroll
                    for (int c = 0; c < 4; c++) acc[r][c] += av[r] * bv[c];
            }
        }

        int cg = n0 + tx * 4;
        float4 bb = { 0.f, 0.f, 0.f, 0.f };
        if (mode & 1) bb = *(const float4*)(bias + cg);
#pragma unroll
        for (int r = 0; r < 4; r++) {
            int rg = m0 + ty * 4 + r;
            float4 v = { acc[r][0] + bb.x, acc[r][1] + bb.y, acc[r][2] + bb.z, acc[r][3] + bb.w };
            if (mode & 2) { v.x = gelu_f(v.x); v.y = gelu_f(v.y); v.z = gelu_f(v.z); v.w = gelu_f(v.w); }
            if (mode & 4) {
                float4 rr = *(const float4*)(res + (size_t)rg * Nc + cg);
                v.x += rr.x; v.y += rr.y; v.z += rr.z; v.w += rr.w;
            }
            *(float4*)(C + (size_t)rg * Nc + cg) = v;
        }
    }
}

// ------------- QK rmsnorm + 2D RoPE + V transpose; 1 warp per (b,h,n) --------
__global__ void qkv_prep(const float* __restrict__ qlin, const float* __restrict__ kv,
                         const float* __restrict__ qg, const float* __restrict__ kg,
                         const int* __restrict__ hidx, const int* __restrict__ widx,
                         float* __restrict__ Q, float* __restrict__ K, float* __restrict__ V)
{
    int warp = (blockIdx.x * blockDim.x + threadIdx.x) >> 5;
    int lane = threadIdx.x & 31;
    int n = warp % N;
    int bh = warp / N;
    int h = bh % H, b = bh / H;

    size_t qsrc = ((size_t)(b * N + n)) * HD + h * DH;
    size_t kvsrc = ((size_t)(b * N + n)) * (2 * HD) + h * DH;
    float q0 = qlin[qsrc + lane], q1 = qlin[qsrc + lane + 32];
    float k0 = kv[kvsrc + lane], k1 = kv[kvsrc + lane + 32];
    float v0 = kv[kvsrc + HD + lane], v1 = kv[kvsrc + HD + lane + 32];

    float qs = q0 * q0 + q1 * q1;
    float ks = k0 * k0 + k1 * k1;
    for (int o = 16; o; o >>= 1) {
        qs += __shfl_xor_sync(0xffffffffu, qs, o);
        ks += __shfl_xor_sync(0xffffffffu, ks, o);
    }
    float rq = 8.0f / fmaxf(sqrtf(qs), 1e-12f);
    float rk = 8.0f / fmaxf(sqrtf(ks), 1e-12f);
    q0 = q0 * rq * qg[h * DH + lane];  q1 = q1 * rq * qg[h * DH + lane + 32];
    k0 = k0 * rk * kg[h * DH + lane];  k1 = k1 * rk * kg[h * DH + lane + 32];

    int hv = hidx[b * N + n], wv = widx[b * N + n];
    int fi = lane & 15;
    float invf = __expf(-(float)fi * (9.210340371976184f / 16.0f));
    float th_h = (float)hv * invf, th_w = (float)wv * invf;
    float sh, chv, sw, cw;
    __sincosf(th_h, &sh, &chv);
    __sincosf(th_w, &sw, &cw);
    float sgn = (lane < 16) ? -1.0f : 1.0f;
    float qp0 = __shfl_xor_sync(0xffffffffu, q0, 16);
    float qp1 = __shfl_xor_sync(0xffffffffu, q1, 16);
    float kp0 = __shfl_xor_sync(0xffffffffu, k0, 16);
    float kp1 = __shfl_xor_sync(0xffffffffu, k1, 16);
    q0 = q0 * chv + sgn * qp0 * sh;
    q1 = q1 * cw + sgn * qp1 * sw;
    k0 = k0 * chv + sgn * kp0 * sh;
    k1 = k1 * cw + sgn * kp1 * sw;

    size_t dst = ((size_t)bh * N + n) * DH;
    Q[dst + lane] = q0; Q[dst + lane + 32] = q1;
    K[dst + lane] = k0; K[dst + lane + 32] = k1;
    V[dst + lane] = v0; V[dst + lane + 32] = v1;
}

// ------------- attention: mma flash, 64 queries/block, 64-key tiles ----------
#define KS_LD 68
#define VS_LD 72

__global__ __launch_bounds__(128, 2)
void attn_mma(const float* __restrict__ Q, const float* __restrict__ K,
              const float* __restrict__ V, const int* __restrict__ lengths,
              float* __restrict__ O)
{
    extern __shared__ float sm[];
    float* Khi = sm;
    float* Klo = Khi + 64 * KS_LD;
    float* Vhi = Klo + 64 * KS_LD;
    float* Vlo = Vhi + 64 * VS_LD;

    int bh = blockIdx.y;
    int b = bh / H, h = bh % H;
    int warp = threadIdx.x >> 5, lane = threadIdx.x & 31;
    int g = lane >> 2, t = lane & 3;
    int q0 = blockIdx.x * 64 + warp * 16;
    int len = lengths[b];

    const float* Qb = Q + (size_t)bh * N * DH;
    const float* Kb = K + (size_t)bh * N * DH;
    const float* Vb = V + (size_t)bh * N * DH;

    unsigned qhi[8][4], qlo[8][4];
#pragma unroll
    for (int kk = 0; kk < 8; kk++) {
        float f0 = Qb[(size_t)(q0 + g)     * DH + kk * 8 + t];
        float f1 = Qb[(size_t)(q0 + 8 + g) * DH + kk * 8 + t];
        float f2 = Qb[(size_t)(q0 + g)     * DH + kk * 8 + t + 4];
        float f3 = Qb[(size_t)(q0 + 8 + g) * DH + kk * 8 + t + 4];
        qhi[kk][0] = f2tf(f0); qlo[kk][0] = f2tf(f0 - __uint_as_float(qhi[kk][0]));
        qhi[kk][1] = f2tf(f1); qlo[kk][1] = f2tf(f1 - __uint_as_float(qhi[kk][1]));
        qhi[kk][2] = f2tf(f2); qlo[kk][2] = f2tf(f2 - __uint_as_float(qhi[kk][2]));
        qhi[kk][3] = f2tf(f3); qlo[kk][3] = f2tf(f3 - __uint_as_float(qhi[kk][3]));
    }

    float oacc[8][4];
#pragma unroll
    for (int dt = 0; dt < 8; dt++)
#pragma unroll
        for (int i = 0; i < 4; i++) oacc[dt][i] = 0.f;
    float m0 = -1e30f, m1 = -1e30f, l0 = 0.f, l1 = 0.f;

    for (int k0 = 0; k0 < len; k0 += 64) {
        __syncthreads();
#pragma unroll
        for (int i = 0; i < 8; i++) {
            int idx = threadIdx.x + i * 128;
            int row = idx >> 4, c4 = (idx & 15) * 4;
            int jj = k0 + row; if (jj > N - 1) jj = N - 1;
            float4 kv4 = *(const float4*)(Kb + (size_t)jj * DH + c4);
            float4 vv4 = *(const float4*)(Vb + (size_t)jj * DH + c4);
            float* kh = Khi + row * KS_LD + c4;
            float* kl = Klo + row * KS_LD + c4;
            float* vh = Vhi + row * VS_LD + c4;
            float* vl = Vlo + row * VS_LD + c4;
            float kvv[4] = { kv4.x, kv4.y, kv4.z, kv4.w };
            float vvv[4] = { vv4.x, vv4.y, vv4.z, vv4.w };
#pragma unroll
            for (int j = 0; j < 4; j++) {
                unsigned hbits = f2tf(kvv[j]);
                kh[j] = __uint_as_float(hbits);
                kl[j] = __uint_as_float(f2tf(kvv[j] - __uint_as_float(hbits)));
                unsigned vb = f2tf(vvv[j]);
                vh[j] = __uint_as_float(vb);
                vl[j] = __uint_as_float(f2tf(vvv[j] - __uint_as_float(vb)));
            }
        }
        __syncthreads();

        float sc[8][4];
#pragma unroll
        for (int nt = 0; nt < 8; nt++)
#pragma unroll
            for (int i = 0; i < 4; i++) sc[nt][i] = 0.f;
#pragma unroll
        for (int kk = 0; kk < 8; kk++) {
#pragma unroll
            for (int nt = 0; nt < 8; nt++) {
                int kb = (nt * 8 + g) * KS_LD + kk * 8 + t;
                unsigned bh0 = __float_as_uint(Khi[kb]);
                unsigned bh1 = __float_as_uint(Khi[kb + 4]);
                unsigned bl0 = __float_as_uint(Klo[kb]);
                unsigned bl1 = __float_as_uint(Klo[kb + 4]);
                mma_tf32(sc[nt], qhi[kk], bh0, bh1);
                mma_tf32(sc[nt], qhi[kk], bl0, bl1);
                mma_tf32(sc[nt], qlo[kk], bh0, bh1);
            }
        }

        float mx0 = -1e30f, mx1 = -1e30f;
#pragma unroll
        for (int nt = 0; nt < 8; nt++) {
            int j = k0 + nt * 8 + 2 * t;
            if (j >= len)     { sc[nt][0] = -1e30f; sc[nt][2] = -1e30f; }
            if (j + 1 >= len) { sc[nt][1] = -1e30f; sc[nt][3] = -1e30f; }
            mx0 = fmaxf(mx0, fmaxf(sc[nt][0], sc[nt][1]));
            mx1 = fmaxf(mx1, fmaxf(sc[nt][2], sc[nt][3]));
        }
        mx0 = fmaxf(mx0, __shfl_xor_sync(0xffffffffu, mx0, 1));
        mx0 = fmaxf(mx0, __shfl_xor_sync(0xffffffffu, mx0, 2));
        mx1 = fmaxf(mx1, __shfl_xor_sync(0xffffffffu, mx1, 1));
        mx1 = fmaxf(mx1, __shfl_xor_sync(0xffffffffu, mx1, 2));
        float mn0 = fmaxf(m0, mx0), mn1 = fmaxf(m1, mx1);
        float scl0 = __expf(m0 - mn0), scl1 = __expf(m1 - mn1);
        float s0 = 0.f, s1 = 0.f;
#pragma unroll
        for (int nt = 0; nt < 8; nt++) {
            sc[nt][0] = __expf(sc[nt][0] - mn0);
            sc[nt][1] = __expf(sc[nt][1] - mn0);
            sc[nt][2] = __expf(sc[nt][2] - mn1);
            sc[nt][3] = __expf(sc[nt][3] - mn1);
            s0 += sc[nt][0] + sc[nt][1];
            s1 += sc[nt][2] + sc[nt][3];
        }
        s0 += __shfl_xor_sync(0xffffffffu, s0, 1);
        s0 += __shfl_xor_sync(0xffffffffu, s0, 2);
        s1 += __shfl_xor_sync(0xffffffffu, s1, 1);
        s1 += __shfl_xor_sync(0xffffffffu, s1, 2);
        l0 = l0 * scl0 + s0;
        l1 = l1 * scl1 + s1;
#pragma unroll
        for (int dt = 0; dt < 8; dt++) {
            oacc[dt][0] *= scl0; oacc[dt][1] *= scl0;
            oacc[dt][2] *= scl1; oacc[dt][3] *= scl1;
        }
        m0 = mn0; m1 = mn1;

#pragma unroll
        for (int kc = 0; kc < 8; kc++) {
            int src0 = (g << 2) + (t >> 1);
            int src1 = src0 + 2;
            float v00 = __shfl_sync(0xffffffffu, sc[kc][0], src0);
            float v01 = __shfl_sync(0xffffffffu, sc[kc][1], src0);
            float v10 = __shfl_sync(0xffffffffu, sc[kc][2], src0);
            float v11 = __shfl_sync(0xffffffffu, sc[kc][3], src0);
            float w00 = __shfl_sync(0xffffffffu, sc[kc][0], src1);
            float w01 = __shfl_sync(0xffffffffu, sc[kc][1], src1);
            float w10 = __shfl_sync(0xffffffffu, sc[kc][2], src1);
            float w11 = __shfl_sync(0xffffffffu, sc[kc][3], src1);
            bool odd = t & 1;
            unsigned a[4];
            a[0] = f2tf(odd ? v01 : v00);
            a[1] = f2tf(odd ? v11 : v10);
            a[2] = f2tf(odd ? w01 : w00);
            a[3] = f2tf(odd ? w11 : w10);
#pragma unroll
            for (int dt = 0; dt < 8; dt++) {
                int vb = (kc * 8 + t) * VS_LD + dt * 8 + g;
                unsigned bh0 = __float_as_uint(Vhi[vb]);
                unsigned bh1 = __float_as_uint(Vhi[vb + 4 * VS_LD]);
                unsigned bl0 = __float_as_uint(Vlo[vb]);
                unsigned bl1 = __float_as_uint(Vlo[vb + 4 * VS_LD]);
                mma_tf32(oacc[dt], a, bh0, bh1);
                mma_tf32(oacc[dt], a, bl0, bl1);
            }
        }
    }

    float il0 = 1.0f / l0, il1 = 1.0f / l1;
    size_t r0 = ((size_t)(b * N + q0 + g)) * HD + h * DH;
    size_t r1 = ((size_t)(b * N + q0 + 8 + g)) * HD + h * DH;
#pragma unroll
    for (int dt = 0; dt < 8; dt++) {
        int col = dt * 8 + 2 * t;
        float2 o0 = { oacc[dt][0] * il0, oacc[dt][1] * il0 };
        float2 o1 = { oacc[dt][2] * il1, oacc[dt][3] * il1 };
        *(float2*)(O + r0 + col) = o0;
        *(float2*)(O + r1 + col) = o1;
    }
}

// ------------- mask output ---------------------------------------------------
__global__ void mask_kernel(const int* __restrict__ lengths, float* __restrict__ out)
{
    int i = blockIdx.x * blockDim.x + threadIdx.x;
    int b = i / N, n = i % N;
    out[i] = (n < lengths[b]) ? 1.0f : 0.0f;
}

// -----------------------------------------------------------------------------
static const int ATTN_SMEM = (2 * 64 * KS_LD + 2 * 64 * VS_LD) * 4; // 71680 B

extern "C" void kernel_launch(void* const* d_in, const int* in_sizes, int n_in,
                              void* d_out, int out_size)
{
    const float* patches    = (const float*)d_in[0];
    const float* pe_ln1_g   = (const float*)d_in[1];
    const float* pe_W       = (const float*)d_in[2];
    const float* pe_b       = (const float*)d_in[3];
    const float* pe_ln2_g   = (const float*)d_in[4];
    const float* attn_ln_g  = (const float*)d_in[5];
    const float* qn_g       = (const float*)d_in[6];
    const float* kn_g       = (const float*)d_in[7];
    const float* Wq         = (const float*)d_in[8];
    const float* Wkv        = (const float*)d_in[9];
    const float* Wo         = (const float*)d_in[10];
    const float* ff_ln_g    = (const float*)d_in[11];
    const float* W1         = (const float*)d_in[12];
    const float* b1         = (const float*)d_in[13];
    const float* W2         = (const float*)d_in[14];
    const float* b2         = (const float*)d_in[15];
    const float* final_ln_g = (const float*)d_in[16];
    const int*   h_idx      = (const int*)d_in[17];
    const int*   w_idx      = (const int*)d_in[18];
    const int*   lengths    = (const int*)d_in[19];
    float* out = (float*)d_out;

    cudaFuncSetAttribute(attn_mma, cudaFuncAttributeMaxDynamicSharedMemorySize, ATTN_SMEM);
    cudaFuncSetAttribute(gemm_hyb, cudaFuncAttributeMaxDynamicSharedMemorySize, GEMM_SMEM);

    float *x, *xn, *qlin, *kv, *Qb, *Kb, *Vb, *att, *hb;
    cudaGetSymbolAddress((void**)&x, g_x);
    cudaGetSymbolAddress((void**)&xn, g_xn);
    cudaGetSymbolAddress((void**)&qlin, g_qlin);
    cudaGetSymbolAddress((void**)&kv, g_kv);
    cudaGetSymbolAddress((void**)&Qb, g_Q);
    cudaGetSymbolAddress((void**)&Kb, g_K);
    cudaGetSymbolAddress((void**)&Vb, g_V);
    cudaGetSymbolAddress((void**)&att, g_att);
    cudaGetSymbolAddress((void**)&hb, g_h);

    // tensor tiles (128 wide) + fma tiles (32 wide), 16.7% fma share
    const int ntDIM = 5,  gxDIM = 5 + 4;    // 640 + 128 = 768
    const int ntKV  = 10, gxKV  = 10 + 8;   // 1280 + 256 = 1536
    const int ntMLP = 20, gxMLP = 20 + 16;  // 2560 + 512 = 3072
    dim3 gDIM(gxDIM, M / 128);
    dim3 gKV(gxKV, M / 128);
    dim3 gMLP(gxMLP, M / 128);

    ln_kernel<<<M / 8, 256>>>(patches, pe_ln1_g, xn);
    gemm_hyb<<<gDIM, 256, GEMM_SMEM>>>(xn, pe_W, pe_b, nullptr, x, DIM, DIM, 1, ntDIM);
    ln_kernel<<<M / 8, 256>>>(x, pe_ln2_g, x);

    for (int i = 0; i < L; i++) {
        const float* Wq_i  = Wq  + (size_t)i * DIM * HD;
        const float* Wkv_i = Wkv + (size_t)i * DIM * 2 * HD;
        const float* Wo_i  = Wo  + (size_t)i * HD * DIM;
        const float* W1_i  = W1  + (size_t)i * DIM * MLP;
        const float* W2_i  = W2  + (size_t)i * MLP * DIM;

        ln_kernel<<<M / 8, 256>>>(x, attn_ln_g + i * DIM, xn);
        gemm_hyb<<<gDIM, 256, GEMM_SMEM>>>(xn, Wq_i, nullptr, nullptr, qlin, DIM, HD, 0, ntDIM);
        gemm_hyb<<<gKV, 256, GEMM_SMEM>>>(xn, Wkv_i, nullptr, nullptr, kv, DIM, 2 * HD, 0, ntKV);
        qkv_prep<<<(B * H * N) / 8, 256>>>(qlin, kv, qn_g + i * H * DH, kn_g + i * H * DH,
                                           h_idx, w_idx, Qb, Kb, Vb);
        attn_mma<<<dim3(N / 64, B * H), 128, ATTN_SMEM>>>(Qb, Kb, Vb, lengths, att);
        gemm_hyb<<<gDIM, 256, GEMM_SMEM>>>(att, Wo_i, nullptr, x, x, HD, DIM, 4, ntDIM);
        ln_kernel<<<M / 8, 256>>>(x, ff_ln_g + i * DIM, xn);
        gemm_hyb<<<gMLP, 256, GEMM_SMEM>>>(xn, W1_i, b1 + i * MLP, nullptr, hb, DIM, MLP, 3, ntMLP);
        gemm_hyb<<<gDIM, 256, GEMM_SMEM>>>(hb, W2_i, b2 + i * DIM, x, x, MLP, DIM, 5, ntDIM);
    }

    ln_kernel<<<M / 8, 256>>>(x, final_ln_g, out);
    if (out_size >= M * DIM + B * N) {
        mask_kernel<<<(B * N) / 256, 256>>>(lengths, out + (size_t)M * DIM);
    }
}

// round 13
// speedup vs baseline: 1.2914x; 1.2914x over previous
#include <cuda_runtime.h>
#include <cuda_fp16.h>
#include <math.h>
#include <stdint.h>

static constexpr int B = 4, N = 2048, DIM = 768, H = 12, DH = 64, MLP = 3072, L = 2;
static constexpr int M = B * N;            // 8192 rows
static constexpr int HD = H * DH;          // 768

// ---------------- scratch (device globals; no allocation allowed) -------------
__device__ float g_x   [M * DIM];
__device__ float g_xn  [M * DIM];
__device__ float g_qlin[M * HD];
__device__ float g_kv  [M * 2 * HD];
__device__ float g_Q   [B * H * N * DH];
__device__ float g_K   [B * H * N * DH];
__device__ float g_V   [B * H * N * DH];
__device__ float g_att [M * HD];
__device__ float g_h   [M * MLP];

// ---------------- helpers ------------------------------------------------------
__device__ __forceinline__ unsigned f2tf(float f) {
    unsigned u; asm("cvt.rna.tf32.f32 %0, %1;" : "=r"(u) : "f"(f)); return u;
}

__device__ __forceinline__ void mma_tf32(float* c, const unsigned* a, unsigned b0, unsigned b1) {
    asm volatile("mma.sync.aligned.m16n8k8.row.col.f32.tf32.tf32.f32 "
                 "{%0,%1,%2,%3}, {%4,%5,%6,%7}, {%8,%9}, {%0,%1,%2,%3};"
                 : "+f"(c[0]), "+f"(c[1]), "+f"(c[2]), "+f"(c[3])
                 : "r"(a[0]), "r"(a[1]), "r"(a[2]), "r"(a[3]), "r"(b0), "r"(b1));
}

__device__ __forceinline__ void mma_f16(float* c, const unsigned* a, unsigned b0, unsigned b1) {
    asm volatile("mma.sync.aligned.m16n8k16.row.col.f32.f16.f16.f32 "
                 "{%0,%1,%2,%3}, {%4,%5,%6,%7}, {%8,%9}, {%0,%1,%2,%3};"
                 : "+f"(c[0]), "+f"(c[1]), "+f"(c[2]), "+f"(c[3])
                 : "r"(a[0]), "r"(a[1]), "r"(a[2]), "r"(a[3]), "r"(b0), "r"(b1));
}

__device__ __forceinline__ unsigned pack_h2(float lo, float hi) {
    __half2 h = __floats2half2_rn(lo, hi);
    return *(unsigned*)&h;
}

__device__ __forceinline__ void cp16(float* smem_dst, const float* gsrc) {
    unsigned d = (unsigned)__cvta_generic_to_shared(smem_dst);
    asm volatile("cp.async.cg.shared.global [%0], [%1], 16;" :: "r"(d), "l"(gsrc));
}
__device__ __forceinline__ void cp_commit() { asm volatile("cp.async.commit_group;"); }
__device__ __forceinline__ void cp_wait0()  { asm volatile("cp.async.wait_group 0;"); }

// ---------------- LayerNorm: one warp per row, DIM=768 -----------------------
__global__ void ln_kernel(const float* __restrict__ in, const float* __restrict__ g,
                          float* __restrict__ out)
{
    int warp = (blockIdx.x * blockDim.x + threadIdx.x) >> 5;
    int lane = threadIdx.x & 31;
    const float* x = in + (size_t)warp * DIM;
    float4 v[6];
    float s = 0.f;
#pragma unroll
    for (int i = 0; i < 6; i++) {
        v[i] = *(const float4*)(x + i * 128 + lane * 4);
        s += v[i].x + v[i].y + v[i].z + v[i].w;
    }
#pragma unroll
    for (int o = 16; o; o >>= 1) s += __shfl_xor_sync(0xffffffffu, s, o);
    float mean = s * (1.0f / DIM);
    float s2 = 0.f;
#pragma unroll
    for (int i = 0; i < 6; i++) {
        float a = v[i].x - mean, b = v[i].y - mean, c = v[i].z - mean, d = v[i].w - mean;
        s2 += a * a + b * b + c * c + d * d;
    }
#pragma unroll
    for (int o = 16; o; o >>= 1) s2 += __shfl_xor_sync(0xffffffffu, s2, o);
    float inv = rsqrtf(s2 * (1.0f / DIM) + 1e-5f);
    float* y = out + (size_t)warp * DIM;
#pragma unroll
    for (int i = 0; i < 6; i++) {
        float4 gg = *(const float4*)(g + i * 128 + lane * 4);
        float4 o4;
        o4.x = (v[i].x - mean) * inv * gg.x;
        o4.y = (v[i].y - mean) * inv * gg.y;
        o4.z = (v[i].z - mean) * inv * gg.z;
        o4.w = (v[i].w - mean) * inv * gg.w;
        *(float4*)(y + i * 128 + lane * 4) = o4;
    }
}

// ---------------- fp16 tensor-core GEMM, cp.async double-buffered -------------
// C[M,Nc] = A[M,K] @ W[K,Nc]; mode bit0:+bias, bit1:gelu, bit2:+res
#define GBM 128
#define GBN 128
#define GBK 32
#define A_LD 36    // floats; 144B = 9*16
#define B_LD 136   // floats; 544B = 34*16
#define ASZ (GBM * A_LD)
#define BSZ (GBK * B_LD)
static const int GEMM_SMEM = 2 * (ASZ + BSZ) * 4;  // 71680 B

__device__ __forceinline__ float gelu_f(float v) {
    return 0.5f * v * (1.0f + erff(v * 0.70710678118654752f));
}

__global__ __launch_bounds__(256, 2)
void gemm_mma(const float* __restrict__ A, const float* __restrict__ W,
              const float* __restrict__ bias, const float* __restrict__ res,
              float* __restrict__ C, int K_, int Nc, int mode)
{
    extern __shared__ float smg[];
    float* Asm[2] = { smg, smg + ASZ };
    float* Bsm[2] = { smg + 2 * ASZ, smg + 2 * ASZ + BSZ };

    int t = threadIdx.x;
    int warp = t >> 5, lane = t & 31;
    int group = lane >> 2, tid = lane & 3;
    int wm = warp >> 1, wn = warp & 1;
    int wr = wm * 32, wc = wn * 64;
    int m0 = blockIdx.y * GBM, n0 = blockIdx.x * GBN;

    int a_row = t >> 3, a_k4 = (t & 7) * 4;
    int b_kr = t >> 5, b_n4 = (t & 31) * 4;

    float acc[2][8][4];
#pragma unroll
    for (int a = 0; a < 2; a++)
#pragma unroll
        for (int b = 0; b < 8; b++)
#pragma unroll
            for (int c = 0; c < 4; c++) acc[a][b][c] = 0.f;

    int KT = K_ / GBK;

    {
        const float* Ab = A + (size_t)m0 * K_;
        const float* Bb = W + n0;
#pragma unroll
        for (int i = 0; i < 4; i++)
            cp16(&Asm[0][(a_row + i * 32) * A_LD + a_k4], Ab + (size_t)(a_row + i * 32) * K_ + a_k4);
#pragma unroll
        for (int i = 0; i < 4; i++)
            cp16(&Bsm[0][(b_kr + i * 8) * B_LD + b_n4], Bb + (size_t)(b_kr + i * 8) * Nc + b_n4);
        cp_commit();
    }

    for (int kt = 0; kt < KT; kt++) {
        cp_wait0();
        __syncthreads();
        if (kt + 1 < KT) {
            int s = (kt + 1) & 1;
            int k0 = (kt + 1) * GBK;
            const float* Ab = A + (size_t)m0 * K_ + k0;
            const float* Bb = W + (size_t)k0 * Nc + n0;
#pragma unroll
            for (int i = 0; i < 4; i++)
                cp16(&Asm[s][(a_row + i * 32) * A_LD + a_k4], Ab + (size_t)(a_row + i * 32) * K_ + a_k4);
#pragma unroll
            for (int i = 0; i < 4; i++)
                cp16(&Bsm[s][(b_kr + i * 8) * B_LD + b_n4], Bb + (size_t)(b_kr + i * 8) * Nc + b_n4);
            cp_commit();
        }
        const float* As = Asm[kt & 1];
        const float* Bs = Bsm[kt & 1];
        // two k16 steps per 32-K tile, m16n8k16 f16 mma
#pragma unroll
        for (int kk = 0; kk < 2; kk++) {
            int k16 = kk * 16;
            unsigned a[2][4];
#pragma unroll
            for (int mt = 0; mt < 2; mt++) {
                int r0 = wr + mt * 16;
                float2 a00 = *(const float2*)&As[(r0 + group) * A_LD + k16 + 2 * tid];
                float2 a10 = *(const float2*)&As[(r0 + 8 + group) * A_LD + k16 + 2 * tid];
                float2 a01 = *(const float2*)&As[(r0 + group) * A_LD + k16 + 2 * tid + 8];
                float2 a11 = *(const float2*)&As[(r0 + 8 + group) * A_LD + k16 + 2 * tid + 8];
                a[mt][0] = pack_h2(a00.x, a00.y);
                a[mt][1] = pack_h2(a10.x, a10.y);
                a[mt][2] = pack_h2(a01.x, a01.y);
                a[mt][3] = pack_h2(a11.x, a11.y);
            }
#pragma unroll
            for (int nt = 0; nt < 8; nt++) {
                int col = wc + nt * 8 + group;
                unsigned b0 = pack_h2(Bs[(k16 + 2 * tid) * B_LD + col],
                                      Bs[(k16 + 2 * tid + 1) * B_LD + col]);
                unsigned b1 = pack_h2(Bs[(k16 + 2 * tid + 8) * B_LD + col],
                                      Bs[(k16 + 2 * tid + 9) * B_LD + col]);
                mma_f16(acc[0][nt], a[0], b0, b1);
                mma_f16(acc[1][nt], a[1], b0, b1);
            }
        }
    }

#pragma unroll
    for (int mt = 0; mt < 2; mt++) {
#pragma unroll
        for (int half = 0; half < 2; half++) {
            int r = m0 + wr + mt * 16 + half * 8 + group;
#pragma unroll
            for (int nt = 0; nt < 8; nt++) {
                int c = n0 + wc + nt * 8 + tid * 2;
                float v0 = acc[mt][nt][half * 2 + 0];
                float v1 = acc[mt][nt][half * 2 + 1];
                if (mode & 1) { v0 += bias[c]; v1 += bias[c + 1]; }
                if (mode & 2) { v0 = gelu_f(v0); v1 = gelu_f(v1); }
                if (mode & 4) {
                    float2 rr = *(const float2*)(res + (size_t)r * Nc + c);
                    v0 += rr.x; v1 += rr.y;
                }
                float2 o = { v0, v1 };
                *(float2*)(C + (size_t)r * Nc + c) = o;
            }
        }
    }
}

// ------------- QK rmsnorm + 2D RoPE + V transpose; 1 warp per (b,h,n) --------
__global__ void qkv_prep(const float* __restrict__ qlin, const float* __restrict__ kv,
                         const float* __restrict__ qg, const float* __restrict__ kg,
                         const int* __restrict__ hidx, const int* __restrict__ widx,
                         float* __restrict__ Q, float* __restrict__ K, float* __restrict__ V)
{
    int warp = (blockIdx.x * blockDim.x + threadIdx.x) >> 5;
    int lane = threadIdx.x & 31;
    int n = warp % N;
    int bh = warp / N;
    int h = bh % H, b = bh / H;

    size_t qsrc = ((size_t)(b * N + n)) * HD + h * DH;
    size_t kvsrc = ((size_t)(b * N + n)) * (2 * HD) + h * DH;
    float q0 = qlin[qsrc + lane], q1 = qlin[qsrc + lane + 32];
    float k0 = kv[kvsrc + lane], k1 = kv[kvsrc + lane + 32];
    float v0 = kv[kvsrc + HD + lane], v1 = kv[kvsrc + HD + lane + 32];

    float qs = q0 * q0 + q1 * q1;
    float ks = k0 * k0 + k1 * k1;
    for (int o = 16; o; o >>= 1) {
        qs += __shfl_xor_sync(0xffffffffu, qs, o);
        ks += __shfl_xor_sync(0xffffffffu, ks, o);
    }
    float rq = 8.0f / fmaxf(sqrtf(qs), 1e-12f);
    float rk = 8.0f / fmaxf(sqrtf(ks), 1e-12f);
    q0 = q0 * rq * qg[h * DH + lane];  q1 = q1 * rq * qg[h * DH + lane + 32];
    k0 = k0 * rk * kg[h * DH + lane];  k1 = k1 * rk * kg[h * DH + lane + 32];

    int hv = hidx[b * N + n], wv = widx[b * N + n];
    int fi = lane & 15;
    float invf = __expf(-(float)fi * (9.210340371976184f / 16.0f));
    float th_h = (float)hv * invf, th_w = (float)wv * invf;
    float sh, chv, sw, cw;
    __sincosf(th_h, &sh, &chv);
    __sincosf(th_w, &sw, &cw);
    float sgn = (lane < 16) ? -1.0f : 1.0f;
    float qp0 = __shfl_xor_sync(0xffffffffu, q0, 16);
    float qp1 = __shfl_xor_sync(0xffffffffu, q1, 16);
    float kp0 = __shfl_xor_sync(0xffffffffu, k0, 16);
    float kp1 = __shfl_xor_sync(0xffffffffu, k1, 16);
    q0 = q0 * chv + sgn * qp0 * sh;
    q1 = q1 * cw + sgn * qp1 * sw;
    k0 = k0 * chv + sgn * kp0 * sh;
    k1 = k1 * cw + sgn * kp1 * sw;

    size_t dst = ((size_t)bh * N + n) * DH;
    Q[dst + lane] = q0; Q[dst + lane + 32] = q1;
    K[dst + lane] = k0; K[dst + lane + 32] = k1;
    V[dst + lane] = v0; V[dst + lane + 32] = v1;
}

// ------------- attention: mma flash, 64 queries/block, 64-key tiles ----------
#define KS_LD 68
#define VS_LD 72

__global__ __launch_bounds__(128, 2)
void attn_mma(const float* __restrict__ Q, const float* __restrict__ K,
              const float* __restrict__ V, const int* __restrict__ lengths,
              float* __restrict__ O)
{
    extern __shared__ float sm[];
    float* Khi = sm;
    float* Klo = Khi + 64 * KS_LD;
    float* Vhi = Klo + 64 * KS_LD;
    float* Vlo = Vhi + 64 * VS_LD;

    int bh = blockIdx.y;
    int b = bh / H, h = bh % H;
    int warp = threadIdx.x >> 5, lane = threadIdx.x & 31;
    int g = lane >> 2, t = lane & 3;
    int q0 = blockIdx.x * 64 + warp * 16;
    int len = lengths[b];

    const float* Qb = Q + (size_t)bh * N * DH;
    const float* Kb = K + (size_t)bh * N * DH;
    const float* Vb = V + (size_t)bh * N * DH;

    unsigned qhi[8][4], qlo[8][4];
#pragma unroll
    for (int kk = 0; kk < 8; kk++) {
        float f0 = Qb[(size_t)(q0 + g)     * DH + kk * 8 + t];
        float f1 = Qb[(size_t)(q0 + 8 + g) * DH + kk * 8 + t];
        float f2 = Qb[(size_t)(q0 + g)     * DH + kk * 8 + t + 4];
        float f3 = Qb[(size_t)(q0 + 8 + g) * DH + kk * 8 + t + 4];
        qhi[kk][0] = f2tf(f0); qlo[kk][0] = f2tf(f0 - __uint_as_float(qhi[kk][0]));
        qhi[kk][1] = f2tf(f1); qlo[kk][1] = f2tf(f1 - __uint_as_float(qhi[kk][1]));
        qhi[kk][2] = f2tf(f2); qlo[kk][2] = f2tf(f2 - __uint_as_float(qhi[kk][2]));
        qhi[kk][3] = f2tf(f3); qlo[kk][3] = f2tf(f3 - __uint_as_float(qhi[kk][3]));
    }

    float oacc[8][4];
#pragma unroll
    for (int dt = 0; dt < 8; dt++)
#pragma unroll
        for (int i = 0; i < 4; i++) oacc[dt][i] = 0.f;
    float m0 = -1e30f, m1 = -1e30f, l0 = 0.f, l1 = 0.f;

    for (int k0 = 0; k0 < len; k0 += 64) {
        __syncthreads();
#pragma unroll
        for (int i = 0; i < 8; i++) {
            int idx = threadIdx.x + i * 128;
            int row = idx >> 4, c4 = (idx & 15) * 4;
            int jj = k0 + row; if (jj > N - 1) jj = N - 1;
            float4 kv4 = *(const float4*)(Kb + (size_t)jj * DH + c4);
            float4 vv4 = *(const float4*)(Vb + (size_t)jj * DH + c4);
            float* kh = Khi + row * KS_LD + c4;
            float* kl = Klo + row * KS_LD + c4;
            float* vh = Vhi + row * VS_LD + c4;
            float* vl = Vlo + row * VS_LD + c4;
            float kvv[4] = { kv4.x, kv4.y, kv4.z, kv4.w };
            float vvv[4] = { vv4.x, vv4.y, vv4.z, vv4.w };
#pragma unroll
            for (int j = 0; j < 4; j++) {
                unsigned hbits = f2tf(kvv[j]);
                kh[j] = __uint_as_float(hbits);
                kl[j] = __uint_as_float(f2tf(kvv[j] - __uint_as_float(hbits)));
                unsigned vb = f2tf(vvv[j]);
                vh[j] = __uint_as_float(vb);
                vl[j] = __uint_as_float(f2tf(vvv[j] - __uint_as_float(vb)));
            }
        }
        __syncthreads();

        float sc[8][4];
#pragma unroll
        for (int nt = 0; nt < 8; nt++)
#pragma unroll
            for (int i = 0; i < 4; i++) sc[nt][i] = 0.f;
#pragma unroll
        for (int kk = 0; kk < 8; kk++) {
#pragma unroll
            for (int nt = 0; nt < 8; nt++) {
                int kb = (nt * 8 + g) * KS_LD + kk * 8 + t;
                unsigned bh0 = __float_as_uint(Khi[kb]);
                unsigned bh1 = __float_as_uint(Khi[kb + 4]);
                unsigned bl0 = __float_as_uint(Klo[kb]);
                unsigned bl1 = __float_as_uint(Klo[kb + 4]);
                mma_tf32(sc[nt], qhi[kk], bh0, bh1);
                mma_tf32(sc[nt], qhi[kk], bl0, bl1);
                mma_tf32(sc[nt], qlo[kk], bh0, bh1);
            }
        }

        float mx0 = -1e30f, mx1 = -1e30f;
#pragma unroll
        for (int nt = 0; nt < 8; nt++) {
            int j = k0 + nt * 8 + 2 * t;
            if (j >= len)     { sc[nt][0] = -1e30f; sc[nt][2] = -1e30f; }
            if (j + 1 >= len) { sc[nt][1] = -1e30f; sc[nt][3] = -1e30f; }
            mx0 = fmaxf(mx0, fmaxf(sc[nt][0], sc[nt][1]));
            mx1 = fmaxf(mx1, fmaxf(sc[nt][2], sc[nt][3]));
        }
        mx0 = fmaxf(mx0, __shfl_xor_sync(0xffffffffu, mx0, 1));
        mx0 = fmaxf(mx0, __shfl_xor_sync(0xffffffffu, mx0, 2));
        mx1 = fmaxf(mx1, __shfl_xor_sync(0xffffffffu, mx1, 1));
        mx1 = fmaxf(mx1, __shfl_xor_sync(0xffffffffu, mx1, 2));
        float mn0 = fmaxf(m0, mx0), mn1 = fmaxf(m1, mx1);
        float scl0 = __expf(m0 - mn0), scl1 = __expf(m1 - mn1);
        float s0 = 0.f, s1 = 0.f;
#pragma unroll
        for (int nt = 0; nt < 8; nt++) {
            sc[nt][0] = __expf(sc[nt][0] - mn0);
            sc[nt][1] = __expf(sc[nt][1] - mn0);
            sc[nt][2] = __expf(sc[nt][2] - mn1);
            sc[nt][3] = __expf(sc[nt][3] - mn1);
            s0 += sc[nt][0] + sc[nt][1];
            s1 += sc[nt][2] + sc[nt][3];
        }
        s0 += __shfl_xor_sync(0xffffffffu, s0, 1);
        s0 += __shfl_xor_sync(0xffffffffu, s0, 2);
        s1 += __shfl_xor_sync(0xffffffffu, s1, 1);
        s1 += __shfl_xor_sync(0xffffffffu, s1, 2);
        l0 = l0 * scl0 + s0;
        l1 = l1 * scl1 + s1;
#pragma unroll
        for (int dt = 0; dt < 8; dt++) {
            oacc[dt][0] *= scl0; oacc[dt][1] *= scl0;
            oacc[dt][2] *= scl1; oacc[dt][3] *= scl1;
        }
        m0 = mn0; m1 = mn1;

#pragma unroll
        for (int kc = 0; kc < 8; kc++) {
            int src0 = (g << 2) + (t >> 1);
            int src1 = src0 + 2;
            float v00 = __shfl_sync(0xffffffffu, sc[kc][0], src0);
            float v01 = __shfl_sync(0xffffffffu, sc[kc][1], src0);
            float v10 = __shfl_sync(0xffffffffu, sc[kc][2], src0);
            float v11 = __shfl_sync(0xffffffffu, sc[kc][3], src0);
            float w00 = __shfl_sync(0xffffffffu, sc[kc][0], src1);
            float w01 = __shfl_sync(0xffffffffu, sc[kc][1], src1);
            float w10 = __shfl_sync(0xffffffffu, sc[kc][2], src1);
            float w11 = __shfl_sync(0xffffffffu, sc[kc][3], src1);
            bool odd = t & 1;
            unsigned a[4];
            a[0] = f2tf(odd ? v01 : v00);
            a[1] = f2tf(odd ? v11 : v10);
            a[2] = f2tf(odd ? w01 : w00);
            a[3] = f2tf(odd ? w11 : w10);
#pragma unroll
            for (int dt = 0; dt < 8; dt++) {
                int vb = (kc * 8 + t) * VS_LD + dt * 8 + g;
                unsigned bh0 = __float_as_uint(Vhi[vb]);
                unsigned bh1 = __float_as_uint(Vhi[vb + 4 * VS_LD]);
                unsigned bl0 = __float_as_uint(Vlo[vb]);
                unsigned bl1 = __float_as_uint(Vlo[vb + 4 * VS_LD]);
                mma_tf32(oacc[dt], a, bh0, bh1);
                mma_tf32(oacc[dt], a, bl0, bl1);
            }
        }
    }

    float il0 = 1.0f / l0, il1 = 1.0f / l1;
    size_t r0 = ((size_t)(b * N + q0 + g)) * HD + h * DH;
    size_t r1 = ((size_t)(b * N + q0 + 8 + g)) * HD + h * DH;
#pragma unroll
    for (int dt = 0; dt < 8; dt++) {
        int col = dt * 8 + 2 * t;
        float2 o0 = { oacc[dt][0] * il0, oacc[dt][1] * il0 };
        float2 o1 = { oacc[dt][2] * il1, oacc[dt][3] * il1 };
        *(float2*)(O + r0 + col) = o0;
        *(float2*)(O + r1 + col) = o1;
    }
}

// ------------- mask output ---------------------------------------------------
__global__ void mask_kernel(const int* __restrict__ lengths, float* __restrict__ out)
{
    int i = blockIdx.x * blockDim.x + threadIdx.x;
    int b = i / N, n = i % N;
    out[i] = (n < lengths[b]) ? 1.0f : 0.0f;
}

// -----------------------------------------------------------------------------
static const int ATTN_SMEM = (2 * 64 * KS_LD + 2 * 64 * VS_LD) * 4; // 71680 B

extern "C" void kernel_launch(void* const* d_in, const int* in_sizes, int n_in,
                              void* d_out, int out_size)
{
    const float* patches    = (const float*)d_in[0];
    const float* pe_ln1_g   = (const float*)d_in[1];
    const float* pe_W       = (const float*)d_in[2];
    const float* pe_b       = (const float*)d_in[3];
    const float* pe_ln2_g   = (const float*)d_in[4];
    const float* attn_ln_g  = (const float*)d_in[5];
    const float* qn_g       = (const float*)d_in[6];
    const float* kn_g       = (const float*)d_in[7];
    const float* Wq         = (const float*)d_in[8];
    const float* Wkv        = (const float*)d_in[9];
    const float* Wo         = (const float*)d_in[10];
    const float* ff_ln_g    = (const float*)d_in[11];
    const float* W1         = (const float*)d_in[12];
    const float* b1         = (const float*)d_in[13];
    const float* W2         = (const float*)d_in[14];
    const float* b2         = (const float*)d_in[15];
    const float* final_ln_g = (const float*)d_in[16];
    const int*   h_idx      = (const int*)d_in[17];
    const int*   w_idx      = (const int*)d_in[18];
    const int*   lengths    = (const int*)d_in[19];
    float* out = (float*)d_out;

    cudaFuncSetAttribute(attn_mma, cudaFuncAttributeMaxDynamicSharedMemorySize, ATTN_SMEM);
    cudaFuncSetAttribute(gemm_mma, cudaFuncAttributeMaxDynamicSharedMemorySize, GEMM_SMEM);

    float *x, *xn, *qlin, *kv, *Qb, *Kb, *Vb, *att, *hb;
    cudaGetSymbolAddress((void**)&x, g_x);
    cudaGetSymbolAddress((void**)&xn, g_xn);
    cudaGetSymbolAddress((void**)&qlin, g_qlin);
    cudaGetSymbolAddress((void**)&kv, g_kv);
    cudaGetSymbolAddress((void**)&Qb, g_Q);
    cudaGetSymbolAddress((void**)&Kb, g_K);
    cudaGetSymbolAddress((void**)&Vb, g_V);
    cudaGetSymbolAddress((void**)&att, g_att);
    cudaGetSymbolAddress((void**)&hb, g_h);

    dim3 gDIM(DIM / 128, M / 128);
    dim3 gKV(2 * HD / 128, M / 128);
    dim3 gMLP(MLP / 128, M / 128);

    ln_kernel<<<M / 8, 256>>>(patches, pe_ln1_g, xn);
    gemm_mma<<<gDIM, 256, GEMM_SMEM>>>(xn, pe_W, pe_b, nullptr, x, DIM, DIM, 1);
    ln_kernel<<<M / 8, 256>>>(x, pe_ln2_g, x);

    for (int i = 0; i < L; i++) {
        const float* Wq_i  = Wq  + (size_t)i * DIM * HD;
        const float* Wkv_i = Wkv + (size_t)i * DIM * 2 * HD;
        const float* Wo_i  = Wo  + (size_t)i * HD * DIM;
        const float* W1_i  = W1  + (size_t)i * DIM * MLP;
        const float* W2_i  = W2  + (size_t)i * MLP * DIM;

        ln_kernel<<<M / 8, 256>>>(x, attn_ln_g + i * DIM, xn);
        gemm_mma<<<gDIM, 256, GEMM_SMEM>>>(xn, Wq_i, nullptr, nullptr, qlin, DIM, HD, 0);
        gemm_mma<<<gKV, 256, GEMM_SMEM>>>(xn, Wkv_i, nullptr, nullptr, kv, DIM, 2 * HD, 0);
        qkv_prep<<<(B * H * N) / 8, 256>>>(qlin, kv, qn_g + i * H * DH, kn_g + i * H * DH,
                                           h_idx, w_idx, Qb, Kb, Vb);
        attn_mma<<<dim3(N / 64, B * H), 128, ATTN_SMEM>>>(Qb, Kb, Vb, lengths, att);
        gemm_mma<<<gDIM, 256, GEMM_SMEM>>>(att, Wo_i, nullptr, x, x, HD, DIM, 4);
        ln_kernel<<<M / 8, 256>>>(x, ff_ln_g + i * DIM, xn);
        gemm_mma<<<gMLP, 256, GEMM_SMEM>>>(xn, W1_i, b1 + i * MLP, nullptr, hb, DIM, MLP, 3);
        gemm_mma<<<gDIM, 256, GEMM_SMEM>>>(hb, W2_i, b2 + i * DIM, x, x, MLP, DIM, 5);
    }

    ln_kernel<<<M / 8, 256>>>(x, final_ln_g, out);
    if (out_size >= M * DIM + B * N) {
        mask_kernel<<<(B * N) / 256, 256>>>(lengths, out + (size_t)M * DIM);
    }
}

// round 14
// speedup vs baseline: 1.5739x; 1.2188x over previous
#include <cuda_runtime.h>
#include <cuda_fp16.h>
#include <math.h>
#include <stdint.h>

static constexpr int B = 4, N = 2048, DIM = 768, H = 12, DH = 64, MLP = 3072, L = 2;
static constexpr int M = B * N;            // 8192 rows
static constexpr int HD = H * DH;          // 768

// ---------------- scratch (device globals; no allocation allowed) -------------
__device__ float  g_x   [M * DIM];
__device__ float  g_qlin[M * HD];
__device__ float  g_kv  [M * 2 * HD];
__device__ float  g_Q   [B * H * N * DH];
__device__ float  g_K   [B * H * N * DH];
__device__ float  g_V   [B * H * N * DH];
__device__ float  g_att [M * HD];
__device__ float  g_h   [M * MLP];
__device__ float2 g_st  [M];               // per-row LN stats (mean, rstd)

// ---------------- helpers ------------------------------------------------------
__device__ __forceinline__ unsigned f2tf(float f) {
    unsigned u; asm("cvt.rna.tf32.f32 %0, %1;" : "=r"(u) : "f"(f)); return u;
}

__device__ __forceinline__ void mma_tf32(float* c, const unsigned* a, unsigned b0, unsigned b1) {
    asm volatile("mma.sync.aligned.m16n8k8.row.col.f32.tf32.tf32.f32 "
                 "{%0,%1,%2,%3}, {%4,%5,%6,%7}, {%8,%9}, {%0,%1,%2,%3};"
                 : "+f"(c[0]), "+f"(c[1]), "+f"(c[2]), "+f"(c[3])
                 : "r"(a[0]), "r"(a[1]), "r"(a[2]), "r"(a[3]), "r"(b0), "r"(b1));
}

__device__ __forceinline__ void mma_f16(float* c, const unsigned* a, unsigned b0, unsigned b1) {
    asm volatile("mma.sync.aligned.m16n8k16.row.col.f32.f16.f16.f32 "
                 "{%0,%1,%2,%3}, {%4,%5,%6,%7}, {%8,%9}, {%0,%1,%2,%3};"
                 : "+f"(c[0]), "+f"(c[1]), "+f"(c[2]), "+f"(c[3])
                 : "r"(a[0]), "r"(a[1]), "r"(a[2]), "r"(a[3]), "r"(b0), "r"(b1));
}

__device__ __forceinline__ unsigned pack_h2(float lo, float hi) {
    __half2 h = __floats2half2_rn(lo, hi);
    return *(unsigned*)&h;
}

// ---------------- LayerNorm: full apply (warp/row) ----------------------------
__global__ void ln_kernel(const float* __restrict__ in, const float* __restrict__ g,
                          float* __restrict__ out)
{
    int warp = (blockIdx.x * blockDim.x + threadIdx.x) >> 5;
    int lane = threadIdx.x & 31;
    const float* x = in + (size_t)warp * DIM;
    float4 v[6];
    float s = 0.f;
#pragma unroll
    for (int i = 0; i < 6; i++) {
        v[i] = *(const float4*)(x + i * 128 + lane * 4);
        s += v[i].x + v[i].y + v[i].z + v[i].w;
    }
#pragma unroll
    for (int o = 16; o; o >>= 1) s += __shfl_xor_sync(0xffffffffu, s, o);
    float mean = s * (1.0f / DIM);
    float s2 = 0.f;
#pragma unroll
    for (int i = 0; i < 6; i++) {
        float a = v[i].x - mean, b = v[i].y - mean, c = v[i].z - mean, d = v[i].w - mean;
        s2 += a * a + b * b + c * c + d * d;
    }
#pragma unroll
    for (int o = 16; o; o >>= 1) s2 += __shfl_xor_sync(0xffffffffu, s2, o);
    float inv = rsqrtf(s2 * (1.0f / DIM) + 1e-5f);
    float* y = out + (size_t)warp * DIM;
#pragma unroll
    for (int i = 0; i < 6; i++) {
        float4 gg = *(const float4*)(g + i * 128 + lane * 4);
        float4 o4;
        o4.x = (v[i].x - mean) * inv * gg.x;
        o4.y = (v[i].y - mean) * inv * gg.y;
        o4.z = (v[i].z - mean) * inv * gg.z;
        o4.w = (v[i].w - mean) * inv * gg.w;
        *(float4*)(y + i * 128 + lane * 4) = o4;
    }
}

// ---------------- LayerNorm stats only (warp/row) -----------------------------
__global__ void ln_stats(const float* __restrict__ in, float2* __restrict__ st)
{
    int warp = (blockIdx.x * blockDim.x + threadIdx.x) >> 5;
    int lane = threadIdx.x & 31;
    const float* x = in + (size_t)warp * DIM;
    float4 v[6];
    float s = 0.f;
#pragma unroll
    for (int i = 0; i < 6; i++) {
        v[i] = *(const float4*)(x + i * 128 + lane * 4);
        s += v[i].x + v[i].y + v[i].z + v[i].w;
    }
#pragma unroll
    for (int o = 16; o; o >>= 1) s += __shfl_xor_sync(0xffffffffu, s, o);
    float mean = s * (1.0f / DIM);
    float s2 = 0.f;
#pragma unroll
    for (int i = 0; i < 6; i++) {
        float a = v[i].x - mean, b = v[i].y - mean, c = v[i].z - mean, d = v[i].w - mean;
        s2 += a * a + b * b + c * c + d * d;
    }
#pragma unroll
    for (int o = 16; o; o >>= 1) s2 += __shfl_xor_sync(0xffffffffu, s2, o);
    float inv = rsqrtf(s2 * (1.0f / DIM) + 1e-5f);
    if (lane == 0) { float2 r = { mean, inv }; st[warp] = r; }
}

// ---------------- fp16 tensor-core GEMM, half2 K-paired smem ------------------
// C[M,Nc] = LN?(A)[M,K] @ W[K,Nc]; mode bit0:+bias, bit1:gelu, bit2:+res
// lnst!=null: apply (a-mean)*rstd*gam at staging (fused LayerNorm).
#define A_LD2 20    // half2 per A row (16 data + 4 pad) -> conflict-free frags
#define B_LD2 136   // half2 per B k2-row (128 data + 8 pad)

__device__ __forceinline__ float gelu_f(float v) {
    return 0.5f * v * (1.0f + erff(v * 0.70710678118654752f));
}

__global__ __launch_bounds__(256, 2)
void gemm_mma(const float* __restrict__ A, const float2* __restrict__ lnst,
              const float* __restrict__ lngam, const float* __restrict__ W,
              const float* __restrict__ bias, const float* __restrict__ res,
              float* __restrict__ C, int K_, int Nc, int mode)
{
    __shared__ unsigned Ah[128 * A_LD2];
    __shared__ unsigned Bh[16 * B_LD2];

    int t = threadIdx.x;
    int warp = t >> 5, lane = t & 31;
    int group = lane >> 2, tid = lane & 3;
    int wm = warp >> 1, wn = warp & 1;
    int wr = wm * 32, wc = wn * 64;
    int m0 = blockIdx.y * 128, n0 = blockIdx.x * 128;

    float acc[2][8][4];
#pragma unroll
    for (int a = 0; a < 2; a++)
#pragma unroll
        for (int b = 0; b < 8; b++)
#pragma unroll
            for (int c = 0; c < 4; c++) acc[a][b][c] = 0.f;

    const float* Arow = A + (size_t)m0 * K_;
    int KT = K_ / 32;

    for (int kt = 0; kt < KT; kt++) {
        int k0 = kt * 32;
        __syncthreads();
        // stage A: 128x32 fp32 -> half2 pairs (LN optionally fused)
#pragma unroll
        for (int i = 0; i < 4; i++) {
            int idx = t + i * 256;
            int row = idx >> 3, k4 = (idx & 7) * 4;
            float4 v = *(const float4*)(Arow + (size_t)row * K_ + k0 + k4);
            if (lnst) {
                float2 s2 = lnst[m0 + row];
                float4 gg = *(const float4*)(lngam + k0 + k4);
                v.x = (v.x - s2.x) * s2.y * gg.x;
                v.y = (v.y - s2.x) * s2.y * gg.y;
                v.z = (v.z - s2.x) * s2.y * gg.z;
                v.w = (v.w - s2.x) * s2.y * gg.w;
            }
            uint2 u = { pack_h2(v.x, v.y), pack_h2(v.z, v.w) };
            *(uint2*)&Ah[row * A_LD2 + (k4 >> 1)] = u;
        }
        // stage B: 32x128 fp32 -> half2 K-pairs (row even = lo, row odd = hi)
#pragma unroll
        for (int i = 0; i < 2; i++) {
            int idx = t + i * 256;
            int k2 = idx >> 5, nq = (idx & 31) * 4;
            const float* p = W + (size_t)(k0 + 2 * k2) * Nc + n0 + nq;
            float4 ve = *(const float4*)p;
            float4 vo = *(const float4*)(p + Nc);
            uint4 u = { pack_h2(ve.x, vo.x), pack_h2(ve.y, vo.y),
                        pack_h2(ve.z, vo.z), pack_h2(ve.w, vo.w) };
            *(uint4*)&Bh[k2 * B_LD2 + nq] = u;
        }
        __syncthreads();
        // two k16 steps, pure LDS.32 -> mma
#pragma unroll
        for (int kk = 0; kk < 2; kk++) {
            int kb = kk * 8;
            unsigned a[2][4];
#pragma unroll
            for (int mt = 0; mt < 2; mt++) {
                int r0 = wr + mt * 16;
                a[mt][0] = Ah[(r0 + group) * A_LD2 + kb + tid];
                a[mt][1] = Ah[(r0 + 8 + group) * A_LD2 + kb + tid];
                a[mt][2] = Ah[(r0 + group) * A_LD2 + kb + tid + 4];
                a[mt][3] = Ah[(r0 + 8 + group) * A_LD2 + kb + tid + 4];
            }
#pragma unroll
            for (int nt = 0; nt < 8; nt++) {
                int col = wc + nt * 8 + group;
                unsigned b0 = Bh[(kb + tid) * B_LD2 + col];
                unsigned b1 = Bh[(kb + tid + 4) * B_LD2 + col];
                mma_f16(acc[0][nt], a[0], b0, b1);
                mma_f16(acc[1][nt], a[1], b0, b1);
            }
        }
    }

#pragma unroll
    for (int mt = 0; mt < 2; mt++) {
#pragma unroll
        for (int half = 0; half < 2; half++) {
            int r = m0 + wr + mt * 16 + half * 8 + group;
#pragma unroll
            for (int nt = 0; nt < 8; nt++) {
                int c = n0 + wc + nt * 8 + tid * 2;
                float v0 = acc[mt][nt][half * 2 + 0];
                float v1 = acc[mt][nt][half * 2 + 1];
                if (mode & 1) { v0 += bias[c]; v1 += bias[c + 1]; }
                if (mode & 2) { v0 = gelu_f(v0); v1 = gelu_f(v1); }
                if (mode & 4) {
                    float2 rr = *(const float2*)(res + (size_t)r * Nc + c);
                    v0 += rr.x; v1 += rr.y;
                }
                float2 o = { v0, v1 };
                *(float2*)(C + (size_t)r * Nc + c) = o;
            }
        }
    }
}

// ------------- QK rmsnorm + 2D RoPE + V transpose; 1 warp per (b,h,n) --------
__global__ void qkv_prep(const float* __restrict__ qlin, const float* __restrict__ kv,
                         const float* __restrict__ qg, const float* __restrict__ kg,
                         const int* __restrict__ hidx, const int* __restrict__ widx,
                         float* __restrict__ Q, float* __restrict__ K, float* __restrict__ V)
{
    int warp = (blockIdx.x * blockDim.x + threadIdx.x) >> 5;
    int lane = threadIdx.x & 31;
    int n = warp % N;
    int bh = warp / N;
    int h = bh % H, b = bh / H;

    size_t qsrc = ((size_t)(b * N + n)) * HD + h * DH;
    size_t kvsrc = ((size_t)(b * N + n)) * (2 * HD) + h * DH;
    float q0 = qlin[qsrc + lane], q1 = qlin[qsrc + lane + 32];
    float k0 = kv[kvsrc + lane], k1 = kv[kvsrc + lane + 32];
    float v0 = kv[kvsrc + HD + lane], v1 = kv[kvsrc + HD + lane + 32];

    float qs = q0 * q0 + q1 * q1;
    float ks = k0 * k0 + k1 * k1;
    for (int o = 16; o; o >>= 1) {
        qs += __shfl_xor_sync(0xffffffffu, qs, o);
        ks += __shfl_xor_sync(0xffffffffu, ks, o);
    }
    float rq = 8.0f / fmaxf(sqrtf(qs), 1e-12f);
    float rk = 8.0f / fmaxf(sqrtf(ks), 1e-12f);
    q0 = q0 * rq * qg[h * DH + lane];  q1 = q1 * rq * qg[h * DH + lane + 32];
    k0 = k0 * rk * kg[h * DH + lane];  k1 = k1 * rk * kg[h * DH + lane + 32];

    int hv = hidx[b * N + n], wv = widx[b * N + n];
    int fi = lane & 15;
    float invf = __expf(-(float)fi * (9.210340371976184f / 16.0f));
    float th_h = (float)hv * invf, th_w = (float)wv * invf;
    float sh, chv, sw, cw;
    __sincosf(th_h, &sh, &chv);
    __sincosf(th_w, &sw, &cw);
    float sgn = (lane < 16) ? -1.0f : 1.0f;
    float qp0 = __shfl_xor_sync(0xffffffffu, q0, 16);
    float qp1 = __shfl_xor_sync(0xffffffffu, q1, 16);
    float kp0 = __shfl_xor_sync(0xffffffffu, k0, 16);
    float kp1 = __shfl_xor_sync(0xffffffffu, k1, 16);
    q0 = q0 * chv + sgn * qp0 * sh;
    q1 = q1 * cw + sgn * qp1 * sw;
    k0 = k0 * chv + sgn * kp0 * sh;
    k1 = k1 * cw + sgn * kp1 * sw;

    size_t dst = ((size_t)bh * N + n) * DH;
    Q[dst + lane] = q0; Q[dst + lane + 32] = q1;
    K[dst + lane] = k0; K[dst + lane + 32] = k1;
    V[dst + lane] = v0; V[dst + lane + 32] = v1;
}

// ------------- attention: mma flash; QK 3xTF32, PV 1xTF32 --------------------
#define KS_LD 68
#define VS_LD 72

__global__ __launch_bounds__(128, 2)
void attn_mma(const float* __restrict__ Q, const float* __restrict__ K,
              const float* __restrict__ V, const int* __restrict__ lengths,
              float* __restrict__ O)
{
    extern __shared__ float sm[];
    float* Khi = sm;
    float* Klo = Khi + 64 * KS_LD;
    float* Vhi = Klo + 64 * KS_LD;

    int bh = blockIdx.y;
    int b = bh / H, h = bh % H;
    int warp = threadIdx.x >> 5, lane = threadIdx.x & 31;
    int g = lane >> 2, t = lane & 3;
    int q0 = blockIdx.x * 64 + warp * 16;
    int len = lengths[b];

    const float* Qb = Q + (size_t)bh * N * DH;
    const float* Kb = K + (size_t)bh * N * DH;
    const float* Vb = V + (size_t)bh * N * DH;

    unsigned qhi[8][4], qlo[8][4];
#pragma unroll
    for (int kk = 0; kk < 8; kk++) {
        float f0 = Qb[(size_t)(q0 + g)     * DH + kk * 8 + t];
        float f1 = Qb[(size_t)(q0 + 8 + g) * DH + kk * 8 + t];
        float f2 = Qb[(size_t)(q0 + g)     * DH + kk * 8 + t + 4];
        float f3 = Qb[(size_t)(q0 + 8 + g) * DH + kk * 8 + t + 4];
        qhi[kk][0] = f2tf(f0); qlo[kk][0] = f2tf(f0 - __uint_as_float(qhi[kk][0]));
        qhi[kk][1] = f2tf(f1); qlo[kk][1] = f2tf(f1 - __uint_as_float(qhi[kk][1]));
        qhi[kk][2] = f2tf(f2); qlo[kk][2] = f2tf(f2 - __uint_as_float(qhi[kk][2]));
        qhi[kk][3] = f2tf(f3); qlo[kk][3] = f2tf(f3 - __uint_as_float(qhi[kk][3]));
    }

    float oacc[8][4];
#pragma unroll
    for (int dt = 0; dt < 8; dt++)
#pragma unroll
        for (int i = 0; i < 4; i++) oacc[dt][i] = 0.f;
    float m0 = -1e30f, m1 = -1e30f, l0 = 0.f, l1 = 0.f;

    for (int k0 = 0; k0 < len; k0 += 64) {
        __syncthreads();
#pragma unroll
        for (int i = 0; i < 8; i++) {
            int idx = threadIdx.x + i * 128;
            int row = idx >> 4, c4 = (idx & 15) * 4;
            int jj = k0 + row; if (jj > N - 1) jj = N - 1;
            float4 kv4 = *(const float4*)(Kb + (size_t)jj * DH + c4);
            float4 vv4 = *(const float4*)(Vb + (size_t)jj * DH + c4);
            float* kh = Khi + row * KS_LD + c4;
            float* kl = Klo + row * KS_LD + c4;
            float* vh = Vhi + row * VS_LD + c4;
            float kvv[4] = { kv4.x, kv4.y, kv4.z, kv4.w };
            float vvv[4] = { vv4.x, vv4.y, vv4.z, vv4.w };
#pragma unroll
            for (int j = 0; j < 4; j++) {
                unsigned hbits = f2tf(kvv[j]);
                kh[j] = __uint_as_float(hbits);
                kl[j] = __uint_as_float(f2tf(kvv[j] - __uint_as_float(hbits)));
                vh[j] = __uint_as_float(f2tf(vvv[j]));
            }
        }
        __syncthreads();

        float sc[8][4];
#pragma unroll
        for (int nt = 0; nt < 8; nt++)
#pragma unroll
            for (int i = 0; i < 4; i++) sc[nt][i] = 0.f;
#pragma unroll
        for (int kk = 0; kk < 8; kk++) {
#pragma unroll
            for (int nt = 0; nt < 8; nt++) {
                int kb = (nt * 8 + g) * KS_LD + kk * 8 + t;
                unsigned bh0 = __float_as_uint(Khi[kb]);
                unsigned bh1 = __float_as_uint(Khi[kb + 4]);
                unsigned bl0 = __float_as_uint(Klo[kb]);
                unsigned bl1 = __float_as_uint(Klo[kb + 4]);
                mma_tf32(sc[nt], qhi[kk], bh0, bh1);
                mma_tf32(sc[nt], qhi[kk], bl0, bl1);
                mma_tf32(sc[nt], qlo[kk], bh0, bh1);
            }
        }

        float mx0 = -1e30f, mx1 = -1e30f;
#pragma unroll
        for (int nt = 0; nt < 8; nt++) {
            int j = k0 + nt * 8 + 2 * t;
            if (j >= len)     { sc[nt][0] = -1e30f; sc[nt][2] = -1e30f; }
            if (j + 1 >= len) { sc[nt][1] = -1e30f; sc[nt][3] = -1e30f; }
            mx0 = fmaxf(mx0, fmaxf(sc[nt][0], sc[nt][1]));
            mx1 = fmaxf(mx1, fmaxf(sc[nt][2], sc[nt][3]));
        }
        mx0 = fmaxf(mx0, __shfl_xor_sync(0xffffffffu, mx0, 1));
        mx0 = fmaxf(mx0, __shfl_xor_sync(0xffffffffu, mx0, 2));
        mx1 = fmaxf(mx1, __shfl_xor_sync(0xffffffffu, mx1, 1));
        mx1 = fmaxf(mx1, __shfl_xor_sync(0xffffffffu, mx1, 2));
        float mn0 = fmaxf(m0, mx0), mn1 = fmaxf(m1, mx1);
        float scl0 = __expf(m0 - mn0), scl1 = __expf(m1 - mn1);
        float s0 = 0.f, s1 = 0.f;
#pragma unroll
        for (int nt = 0; nt < 8; nt++) {
            sc[nt][0] = __expf(sc[nt][0] - mn0);
            sc[nt][1] = __expf(sc[nt][1] - mn0);
            sc[nt][2] = __expf(sc[nt][2] - mn1);
            sc[nt][3] = __expf(sc[nt][3] - mn1);
            s0 += sc[nt][0] + sc[nt][1];
            s1 += sc[nt][2] + sc[nt][3];
        }
        s0 += __shfl_xor_sync(0xffffffffu, s0, 1);
        s0 += __shfl_xor_sync(0xffffffffu, s0, 2);
        s1 += __shfl_xor_sync(0xffffffffu, s1, 1);
        s1 += __shfl_xor_sync(0xffffffffu, s1, 2);
        l0 = l0 * scl0 + s0;
        l1 = l1 * scl1 + s1;
#pragma unroll
        for (int dt = 0; dt < 8; dt++) {
            oacc[dt][0] *= scl0; oacc[dt][1] *= scl0;
            oacc[dt][2] *= scl1; oacc[dt][3] *= scl1;
        }
        m0 = mn0; m1 = mn1;

#pragma unroll
        for (int kc = 0; kc < 8; kc++) {
            int src0 = (g << 2) + (t >> 1);
            int src1 = src0 + 2;
            float v00 = __shfl_sync(0xffffffffu, sc[kc][0], src0);
            float v01 = __shfl_sync(0xffffffffu, sc[kc][1], src0);
            float v10 = __shfl_sync(0xffffffffu, sc[kc][2], src0);
            float v11 = __shfl_sync(0xffffffffu, sc[kc][3], src0);
            float w00 = __shfl_sync(0xffffffffu, sc[kc][0], src1);
            float w01 = __shfl_sync(0xffffffffu, sc[kc][1], src1);
            float w10 = __shfl_sync(0xffffffffu, sc[kc][2], src1);
            float w11 = __shfl_sync(0xffffffffu, sc[kc][3], src1);
            bool odd = t & 1;
            unsigned a[4];
            a[0] = f2tf(odd ? v01 : v00);
            a[1] = f2tf(odd ? v11 : v10);
            a[2] = f2tf(odd ? w01 : w00);
            a[3] = f2tf(odd ? w11 : w10);
#pragma unroll
            for (int dt = 0; dt < 8; dt++) {
                int vb = (kc * 8 + t) * VS_LD + dt * 8 + g;
                unsigned bh0 = __float_as_uint(Vhi[vb]);
                unsigned bh1 = __float_as_uint(Vhi[vb + 4 * VS_LD]);
                mma_tf32(oacc[dt], a, bh0, bh1);
            }
        }
    }

    float il0 = 1.0f / l0, il1 = 1.0f / l1;
    size_t r0 = ((size_t)(b * N + q0 + g)) * HD + h * DH;
    size_t r1 = ((size_t)(b * N + q0 + 8 + g)) * HD + h * DH;
#pragma unroll
    for (int dt = 0; dt < 8; dt++) {
        int col = dt * 8 + 2 * t;
        float2 o0 = { oacc[dt][0] * il0, oacc[dt][1] * il0 };
        float2 o1 = { oacc[dt][2] * il1, oacc[dt][3] * il1 };
        *(float2*)(O + r0 + col) = o0;
        *(float2*)(O + r1 + col) = o1;
    }
}

// ------------- mask output ---------------------------------------------------
__global__ void mask_kernel(const int* __restrict__ lengths, float* __restrict__ out)
{
    int i = blockIdx.x * blockDim.x + threadIdx.x;
    int b = i / N, n = i % N;
    out[i] = (n < lengths[b]) ? 1.0f : 0.0f;
}

// -----------------------------------------------------------------------------
static const int ATTN_SMEM = (2 * 64 * KS_LD + 64 * VS_LD) * 4; // 53248 B

extern "C" void kernel_launch(void* const* d_in, const int* in_sizes, int n_in,
                              void* d_out, int out_size)
{
    const float* patches    = (const float*)d_in[0];
    const float* pe_ln1_g   = (const float*)d_in[1];
    const float* pe_W       = (const float*)d_in[2];
    const float* pe_b       = (const float*)d_in[3];
    const float* pe_ln2_g   = (const float*)d_in[4];
    const float* attn_ln_g  = (const float*)d_in[5];
    const float* qn_g       = (const float*)d_in[6];
    const float* kn_g       = (const float*)d_in[7];
    const float* Wq         = (const float*)d_in[8];
    const float* Wkv        = (const float*)d_in[9];
    const float* Wo         = (const float*)d_in[10];
    const float* ff_ln_g    = (const float*)d_in[11];
    const float* W1         = (const float*)d_in[12];
    const float* b1         = (const float*)d_in[13];
    const float* W2         = (const float*)d_in[14];
    const float* b2         = (const float*)d_in[15];
    const float* final_ln_g = (const float*)d_in[16];
    const int*   h_idx      = (const int*)d_in[17];
    const int*   w_idx      = (const int*)d_in[18];
    const int*   lengths    = (const int*)d_in[19];
    float* out = (float*)d_out;

    cudaFuncSetAttribute(attn_mma, cudaFuncAttributeMaxDynamicSharedMemorySize, ATTN_SMEM);

    float *x, *qlin, *kv, *Qb, *Kb, *Vb, *att, *hb;
    float2* st;
    cudaGetSymbolAddress((void**)&x, g_x);
    cudaGetSymbolAddress((void**)&qlin, g_qlin);
    cudaGetSymbolAddress((void**)&kv, g_kv);
    cudaGetSymbolAddress((void**)&Qb, g_Q);
    cudaGetSymbolAddress((void**)&Kb, g_K);
    cudaGetSymbolAddress((void**)&Vb, g_V);
    cudaGetSymbolAddress((void**)&att, g_att);
    cudaGetSymbolAddress((void**)&hb, g_h);
    cudaGetSymbolAddress((void**)&st, g_st);

    dim3 gDIM(DIM / 128, M / 128);
    dim3 gKV(2 * HD / 128, M / 128);
    dim3 gMLP(MLP / 128, M / 128);

    // patch embedding: LN (fused) -> Linear+bias -> LN
    ln_stats<<<M / 8, 256>>>(patches, st);
    gemm_mma<<<gDIM, 256>>>(patches, st, pe_ln1_g, pe_W, pe_b, nullptr, x, DIM, DIM, 1);
    ln_kernel<<<M / 8, 256>>>(x, pe_ln2_g, x);

    for (int i = 0; i < L; i++) {
        const float* Wq_i  = Wq  + (size_t)i * DIM * HD;
        const float* Wkv_i = Wkv + (size_t)i * DIM * 2 * HD;
        const float* Wo_i  = Wo  + (size_t)i * HD * DIM;
        const float* W1_i  = W1  + (size_t)i * DIM * MLP;
        const float* W2_i  = W2  + (size_t)i * MLP * DIM;

        ln_stats<<<M / 8, 256>>>(x, st);
        gemm_mma<<<gDIM, 256>>>(x, st, attn_ln_g + i * DIM, Wq_i, nullptr, nullptr, qlin, DIM, HD, 0);
        gemm_mma<<<gKV, 256>>>(x, st, attn_ln_g + i * DIM, Wkv_i, nullptr, nullptr, kv, DIM, 2 * HD, 0);
        qkv_prep<<<(B * H * N) / 8, 256>>>(qlin, kv, qn_g + i * H * DH, kn_g + i * H * DH,
                                           h_idx, w_idx, Qb, Kb, Vb);
        attn_mma<<<dim3(N / 64, B * H), 128, ATTN_SMEM>>>(Qb, Kb, Vb, lengths, att);
        gemm_mma<<<gDIM, 256>>>(att, nullptr, nullptr, Wo_i, nullptr, x, x, HD, DIM, 4);
        ln_stats<<<M / 8, 256>>>(x, st);
        gemm_mma<<<gMLP, 256>>>(x, st, ff_ln_g + i * DIM, W1_i, b1 + i * MLP, nullptr, hb, DIM, MLP, 3);
        gemm_mma<<<gDIM, 256>>>(hb, nullptr, nullptr, W2_i, b2 + i * DIM, x, x, MLP, DIM, 5);
    }

    ln_kernel<<<M / 8, 256>>>(x, final_ln_g, out);
    if (out_size >= M * DIM + B * N) {
        mask_kernel<<<(B * N) / 256, 256>>>(lengths, out + (size_t)M * DIM);
    }
}

// round 15
// speedup vs baseline: 1.7571x; 1.1164x over previous
#include <cuda_runtime.h>
#include <cuda_fp16.h>
#include <math.h>
#include <stdint.h>

static constexpr int B = 4, N = 2048, DIM = 768, H = 12, DH = 64, MLP = 3072, L = 2;
static constexpr int M = B * N;            // 8192 rows
static constexpr int HD = H * DH;          // 768

// ---------------- scratch (device globals; no allocation allowed) -------------
__device__ float  g_x   [M * DIM];
__device__ float  g_qlin[M * HD];
__device__ float  g_kv  [M * 2 * HD];
__device__ float  g_Q   [B * H * N * DH];
__device__ float  g_K   [B * H * N * DH];
__device__ float  g_V   [B * H * N * DH];
__device__ float  g_att [M * HD];
__device__ float  g_h   [M * MLP];
__device__ float2 g_st  [M];               // per-row LN stats (mean, rstd)

// ---------------- helpers ------------------------------------------------------
__device__ __forceinline__ unsigned f2tf(float f) {
    unsigned u; asm("cvt.rna.tf32.f32 %0, %1;" : "=r"(u) : "f"(f)); return u;
}

__device__ __forceinline__ void mma_tf32(float* c, const unsigned* a, unsigned b0, unsigned b1) {
    asm volatile("mma.sync.aligned.m16n8k8.row.col.f32.tf32.tf32.f32 "
                 "{%0,%1,%2,%3}, {%4,%5,%6,%7}, {%8,%9}, {%0,%1,%2,%3};"
                 : "+f"(c[0]), "+f"(c[1]), "+f"(c[2]), "+f"(c[3])
                 : "r"(a[0]), "r"(a[1]), "r"(a[2]), "r"(a[3]), "r"(b0), "r"(b1));
}

__device__ __forceinline__ void mma_f16(float* c, const unsigned* a, unsigned b0, unsigned b1) {
    asm volatile("mma.sync.aligned.m16n8k16.row.col.f32.f16.f16.f32 "
                 "{%0,%1,%2,%3}, {%4,%5,%6,%7}, {%8,%9}, {%0,%1,%2,%3};"
                 : "+f"(c[0]), "+f"(c[1]), "+f"(c[2]), "+f"(c[3])
                 : "r"(a[0]), "r"(a[1]), "r"(a[2]), "r"(a[3]), "r"(b0), "r"(b1));
}

__device__ __forceinline__ unsigned pack_h2(float lo, float hi) {
    __half2 h = __floats2half2_rn(lo, hi);
    return *(unsigned*)&h;
}

// ---------------- LayerNorm: full apply (warp/row) ----------------------------
__global__ void ln_kernel(const float* __restrict__ in, const float* __restrict__ g,
                          float* __restrict__ out)
{
    int warp = (blockIdx.x * blockDim.x + threadIdx.x) >> 5;
    int lane = threadIdx.x & 31;
    const float* x = in + (size_t)warp * DIM;
    float4 v[6];
    float s = 0.f;
#pragma unroll
    for (int i = 0; i < 6; i++) {
        v[i] = *(const float4*)(x + i * 128 + lane * 4);
        s += v[i].x + v[i].y + v[i].z + v[i].w;
    }
#pragma unroll
    for (int o = 16; o; o >>= 1) s += __shfl_xor_sync(0xffffffffu, s, o);
    float mean = s * (1.0f / DIM);
    float s2 = 0.f;
#pragma unroll
    for (int i = 0; i < 6; i++) {
        float a = v[i].x - mean, b = v[i].y - mean, c = v[i].z - mean, d = v[i].w - mean;
        s2 += a * a + b * b + c * c + d * d;
    }
#pragma unroll
    for (int o = 16; o; o >>= 1) s2 += __shfl_xor_sync(0xffffffffu, s2, o);
    float inv = rsqrtf(s2 * (1.0f / DIM) + 1e-5f);
    float* y = out + (size_t)warp * DIM;
#pragma unroll
    for (int i = 0; i < 6; i++) {
        float4 gg = *(const float4*)(g + i * 128 + lane * 4);
        float4 o4;
        o4.x = (v[i].x - mean) * inv * gg.x;
        o4.y = (v[i].y - mean) * inv * gg.y;
        o4.z = (v[i].z - mean) * inv * gg.z;
        o4.w = (v[i].w - mean) * inv * gg.w;
        *(float4*)(y + i * 128 + lane * 4) = o4;
    }
}

// ---------------- LayerNorm stats only (warp/row) -----------------------------
__global__ void ln_stats(const float* __restrict__ in, float2* __restrict__ st)
{
    int warp = (blockIdx.x * blockDim.x + threadIdx.x) >> 5;
    int lane = threadIdx.x & 31;
    const float* x = in + (size_t)warp * DIM;
    float4 v[6];
    float s = 0.f;
#pragma unroll
    for (int i = 0; i < 6; i++) {
        v[i] = *(const float4*)(x + i * 128 + lane * 4);
        s += v[i].x + v[i].y + v[i].z + v[i].w;
    }
#pragma unroll
    for (int o = 16; o; o >>= 1) s += __shfl_xor_sync(0xffffffffu, s, o);
    float mean = s * (1.0f / DIM);
    float s2 = 0.f;
#pragma unroll
    for (int i = 0; i < 6; i++) {
        float a = v[i].x - mean, b = v[i].y - mean, c = v[i].z - mean, d = v[i].w - mean;
        s2 += a * a + b * b + c * c + d * d;
    }
#pragma unroll
    for (int o = 16; o; o >>= 1) s2 += __shfl_xor_sync(0xffffffffu, s2, o);
    float inv = rsqrtf(s2 * (1.0f / DIM) + 1e-5f);
    if (lane == 0) { float2 r = { mean, inv }; st[warp] = r; }
}

// ---------------- fp16 GEMM, register-pipelined half2 smem --------------------
// C[M,Nc] = LN?(A)[M,K] @ W[K,Nc]; mode bit0:+bias, bit1:gelu, bit2:+res
#define A_LD2 20    // half2 per A row (16 data + 4 pad)
#define B_LD2 136   // half2 per B k2-row (128 data + 8 pad)

__device__ __forceinline__ float gelu_f(float v) {
    return 0.5f * v * (1.0f + erff(v * 0.70710678118654752f));
}

__global__ __launch_bounds__(256, 2)
void gemm_mma(const float* __restrict__ A, const float2* __restrict__ lnst,
              const float* __restrict__ lngam, const float* __restrict__ W,
              const float* __restrict__ bias, const float* __restrict__ res,
              float* __restrict__ C, int K_, int Nc, int mode)
{
    __shared__ unsigned Ah[2][128 * A_LD2];
    __shared__ unsigned Bh[2][16 * B_LD2];

    int t = threadIdx.x;
    int warp = t >> 5, lane = t & 31;
    int group = lane >> 2, tid = lane & 3;
    int wm = warp >> 1, wn = warp & 1;
    int wr = wm * 32, wc = wn * 64;
    int m0 = blockIdx.y * 128, n0 = blockIdx.x * 128;

    // fixed per-thread staging coords
    int ar0 = t >> 3, ak = (t & 7) * 4;     // A rows ar0 + i*32, cols ak..ak+3
    int bk0 = t >> 5, bn = (t & 31) * 4;    // B k2-rows bk0 + i*8, cols bn..bn+3

    float acc[2][8][4];
#pragma unroll
    for (int a = 0; a < 2; a++)
#pragma unroll
        for (int b = 0; b < 8; b++)
#pragma unroll
            for (int c = 0; c < 4; c++) acc[a][b][c] = 0.f;

    const float* Arow = A + (size_t)m0 * K_;
    float4 ra[4], rbe[2], rbo[2];

    auto ldregs = [&](int k0) {
#pragma unroll
        for (int i = 0; i < 4; i++)
            ra[i] = *(const float4*)(Arow + (size_t)(ar0 + i * 32) * K_ + k0 + ak);
#pragma unroll
        for (int i = 0; i < 2; i++) {
            const float* p = W + (size_t)(k0 + 2 * (bk0 + i * 8)) * Nc + n0 + bn;
            rbe[i] = *(const float4*)p;
            rbo[i] = *(const float4*)(p + Nc);
        }
    };
    auto stsbuf = [&](int s, int k0) {
        float4 gg;
        if (lnst) gg = *(const float4*)(lngam + k0 + ak);
#pragma unroll
        for (int i = 0; i < 4; i++) {
            float4 v = ra[i];
            if (lnst) {
                float2 s2 = lnst[m0 + ar0 + i * 32];
                v.x = (v.x - s2.x) * s2.y * gg.x;
                v.y = (v.y - s2.x) * s2.y * gg.y;
                v.z = (v.z - s2.x) * s2.y * gg.z;
                v.w = (v.w - s2.x) * s2.y * gg.w;
            }
            uint2 u = { pack_h2(v.x, v.y), pack_h2(v.z, v.w) };
            *(uint2*)&Ah[s][(ar0 + i * 32) * A_LD2 + (ak >> 1)] = u;
        }
#pragma unroll
        for (int i = 0; i < 2; i++) {
            uint4 u = { pack_h2(rbe[i].x, rbo[i].x), pack_h2(rbe[i].y, rbo[i].y),
                        pack_h2(rbe[i].z, rbo[i].z), pack_h2(rbe[i].w, rbo[i].w) };
            *(uint4*)&Bh[s][(bk0 + i * 8) * B_LD2 + bn] = u;
        }
    };

    int KT = K_ / 32;
    ldregs(0);
    stsbuf(0, 0);
    __syncthreads();

    for (int kt = 0; kt < KT; kt++) {
        if (kt + 1 < KT) ldregs((kt + 1) * 32);
        const unsigned* As = Ah[kt & 1];
        const unsigned* Bs = Bh[kt & 1];
#pragma unroll
        for (int kk = 0; kk < 2; kk++) {
            int kb = kk * 8;
            unsigned a[2][4];
#pragma unroll
            for (int mt = 0; mt < 2; mt++) {
                int r0 = wr + mt * 16;
                a[mt][0] = As[(r0 + group) * A_LD2 + kb + tid];
                a[mt][1] = As[(r0 + 8 + group) * A_LD2 + kb + tid];
                a[mt][2] = As[(r0 + group) * A_LD2 + kb + tid + 4];
                a[mt][3] = As[(r0 + 8 + group) * A_LD2 + kb + tid + 4];
            }
#pragma unroll
            for (int nt = 0; nt < 8; nt++) {
                int col = wc + nt * 8 + group;
                unsigned b0 = Bs[(kb + tid) * B_LD2 + col];
                unsigned b1 = Bs[(kb + tid + 4) * B_LD2 + col];
                mma_f16(acc[0][nt], a[0], b0, b1);
                mma_f16(acc[1][nt], a[1], b0, b1);
            }
        }
        if (kt + 1 < KT) stsbuf((kt + 1) & 1, (kt + 1) * 32);
        __syncthreads();
    }

#pragma unroll
    for (int mt = 0; mt < 2; mt++) {
#pragma unroll
        for (int half = 0; half < 2; half++) {
            int r = m0 + wr + mt * 16 + half * 8 + group;
#pragma unroll
            for (int nt = 0; nt < 8; nt++) {
                int c = n0 + wc + nt * 8 + tid * 2;
                float v0 = acc[mt][nt][half * 2 + 0];
                float v1 = acc[mt][nt][half * 2 + 1];
                if (mode & 1) { v0 += bias[c]; v1 += bias[c + 1]; }
                if (mode & 2) { v0 = gelu_f(v0); v1 = gelu_f(v1); }
                if (mode & 4) {
                    float2 rr = *(const float2*)(res + (size_t)r * Nc + c);
                    v0 += rr.x; v1 += rr.y;
                }
                float2 o = { v0, v1 };
                *(float2*)(C + (size_t)r * Nc + c) = o;
            }
        }
    }
}

// ------------- QK rmsnorm + 2D RoPE + V transpose; 1 warp per (b,h,n) --------
__global__ void qkv_prep(const float* __restrict__ qlin, const float* __restrict__ kv,
                         const float* __restrict__ qg, const float* __restrict__ kg,
                         const int* __restrict__ hidx, const int* __restrict__ widx,
                         float* __restrict__ Q, float* __restrict__ K, float* __restrict__ V)
{
    int warp = (blockIdx.x * blockDim.x + threadIdx.x) >> 5;
    int lane = threadIdx.x & 31;
    int n = warp % N;
    int bh = warp / N;
    int h = bh % H, b = bh / H;

    size_t qsrc = ((size_t)(b * N + n)) * HD + h * DH;
    size_t kvsrc = ((size_t)(b * N + n)) * (2 * HD) + h * DH;
    float q0 = qlin[qsrc + lane], q1 = qlin[qsrc + lane + 32];
    float k0 = kv[kvsrc + lane], k1 = kv[kvsrc + lane + 32];
    float v0 = kv[kvsrc + HD + lane], v1 = kv[kvsrc + HD + lane + 32];

    float qs = q0 * q0 + q1 * q1;
    float ks = k0 * k0 + k1 * k1;
    for (int o = 16; o; o >>= 1) {
        qs += __shfl_xor_sync(0xffffffffu, qs, o);
        ks += __shfl_xor_sync(0xffffffffu, ks, o);
    }
    float rq = 8.0f / fmaxf(sqrtf(qs), 1e-12f);
    float rk = 8.0f / fmaxf(sqrtf(ks), 1e-12f);
    q0 = q0 * rq * qg[h * DH + lane];  q1 = q1 * rq * qg[h * DH + lane + 32];
    k0 = k0 * rk * kg[h * DH + lane];  k1 = k1 * rk * kg[h * DH + lane + 32];

    int hv = hidx[b * N + n], wv = widx[b * N + n];
    int fi = lane & 15;
    float invf = __expf(-(float)fi * (9.210340371976184f / 16.0f));
    float th_h = (float)hv * invf, th_w = (float)wv * invf;
    float sh, chv, sw, cw;
    __sincosf(th_h, &sh, &chv);
    __sincosf(th_w, &sw, &cw);
    float sgn = (lane < 16) ? -1.0f : 1.0f;
    float qp0 = __shfl_xor_sync(0xffffffffu, q0, 16);
    float qp1 = __shfl_xor_sync(0xffffffffu, q1, 16);
    float kp0 = __shfl_xor_sync(0xffffffffu, k0, 16);
    float kp1 = __shfl_xor_sync(0xffffffffu, k1, 16);
    q0 = q0 * chv + sgn * qp0 * sh;
    q1 = q1 * cw + sgn * qp1 * sw;
    k0 = k0 * chv + sgn * kp0 * sh;
    k1 = k1 * cw + sgn * kp1 * sw;

    size_t dst = ((size_t)bh * N + n) * DH;
    Q[dst + lane] = q0; Q[dst + lane + 32] = q1;
    K[dst + lane] = k0; K[dst + lane + 32] = k1;
    V[dst + lane] = v0; V[dst + lane + 32] = v1;
}

// ------------- attention: mma flash; QK 3xTF32, PV 1xTF32 --------------------
#define KS_LD 68
#define VS_LD 72

__global__ __launch_bounds__(128, 2)
void attn_mma(const float* __restrict__ Q, const float* __restrict__ K,
              const float* __restrict__ V, const int* __restrict__ lengths,
              float* __restrict__ O)
{
    extern __shared__ float sm[];
    float* Khi = sm;
    float* Klo = Khi + 64 * KS_LD;
    float* Vhi = Klo + 64 * KS_LD;

    int bh = blockIdx.y;
    int b = bh / H, h = bh % H;
    int warp = threadIdx.x >> 5, lane = threadIdx.x & 31;
    int g = lane >> 2, t = lane & 3;
    int q0 = blockIdx.x * 64 + warp * 16;
    int len = lengths[b];

    const float* Qb = Q + (size_t)bh * N * DH;
    const float* Kb = K + (size_t)bh * N * DH;
    const float* Vb = V + (size_t)bh * N * DH;

    unsigned qhi[8][4], qlo[8][4];
#pragma unroll
    for (int kk = 0; kk < 8; kk++) {
        float f0 = Qb[(size_t)(q0 + g)     * DH + kk * 8 + t];
        float f1 = Qb[(size_t)(q0 + 8 + g) * DH + kk * 8 + t];
        float f2 = Qb[(size_t)(q0 + g)     * DH + kk * 8 + t + 4];
        float f3 = Qb[(size_t)(q0 + 8 + g) * DH + kk * 8 + t + 4];
        qhi[kk][0] = f2tf(f0); qlo[kk][0] = f2tf(f0 - __uint_as_float(qhi[kk][0]));
        qhi[kk][1] = f2tf(f1); qlo[kk][1] = f2tf(f1 - __uint_as_float(qhi[kk][1]));
        qhi[kk][2] = f2tf(f2); qlo[kk][2] = f2tf(f2 - __uint_as_float(qhi[kk][2]));
        qhi[kk][3] = f2tf(f3); qlo[kk][3] = f2tf(f3 - __uint_as_float(qhi[kk][3]));
    }

    float oacc[8][4];
#pragma unroll
    for (int dt = 0; dt < 8; dt++)
#pragma unroll
        for (int i = 0; i < 4; i++) oacc[dt][i] = 0.f;
    float m0 = -1e30f, m1 = -1e30f, l0 = 0.f, l1 = 0.f;

    for (int k0 = 0; k0 < len; k0 += 64) {
        __syncthreads();
#pragma unroll
        for (int i = 0; i < 8; i++) {
            int idx = threadIdx.x + i * 128;
            int row = idx >> 4, c4 = (idx & 15) * 4;
            int jj = k0 + row; if (jj > N - 1) jj = N - 1;
            float4 kv4 = *(const float4*)(Kb + (size_t)jj * DH + c4);
            float4 vv4 = *(const float4*)(Vb + (size_t)jj * DH + c4);
            float* kh = Khi + row * KS_LD + c4;
            float* kl = Klo + row * KS_LD + c4;
            float* vh = Vhi + row * VS_LD + c4;
            float kvv[4] = { kv4.x, kv4.y, kv4.z, kv4.w };
            float vvv[4] = { vv4.x, vv4.y, vv4.z, vv4.w };
#pragma unroll
            for (int j = 0; j < 4; j++) {
                unsigned hbits = f2tf(kvv[j]);
                kh[j] = __uint_as_float(hbits);
                kl[j] = __uint_as_float(f2tf(kvv[j] - __uint_as_float(hbits)));
                vh[j] = __uint_as_float(f2tf(vvv[j]));
            }
        }
        __syncthreads();

        float sc[8][4];
#pragma unroll
        for (int nt = 0; nt < 8; nt++)
#pragma unroll
            for (int i = 0; i < 4; i++) sc[nt][i] = 0.f;
#pragma unroll
        for (int kk = 0; kk < 8; kk++) {
#pragma unroll
            for (int nt = 0; nt < 8; nt++) {
                int kb = (nt * 8 + g) * KS_LD + kk * 8 + t;
                unsigned bh0 = __float_as_uint(Khi[kb]);
                unsigned bh1 = __float_as_uint(Khi[kb + 4]);
                unsigned bl0 = __float_as_uint(Klo[kb]);
                unsigned bl1 = __float_as_uint(Klo[kb + 4]);
                mma_tf32(sc[nt], qhi[kk], bh0, bh1);
                mma_tf32(sc[nt], qhi[kk], bl0, bl1);
                mma_tf32(sc[nt], qlo[kk], bh0, bh1);
            }
        }

        float mx0 = -1e30f, mx1 = -1e30f;
#pragma unroll
        for (int nt = 0; nt < 8; nt++) {
            int j = k0 + nt * 8 + 2 * t;
            if (j >= len)     { sc[nt][0] = -1e30f; sc[nt][2] = -1e30f; }
            if (j + 1 >= len) { sc[nt][1] = -1e30f; sc[nt][3] = -1e30f; }
            mx0 = fmaxf(mx0, fmaxf(sc[nt][0], sc[nt][1]));
            mx1 = fmaxf(mx1, fmaxf(sc[nt][2], sc[nt][3]));
        }
        mx0 = fmaxf(mx0, __shfl_xor_sync(0xffffffffu, mx0, 1));
        mx0 = fmaxf(mx0, __shfl_xor_sync(0xffffffffu, mx0, 2));
        mx1 = fmaxf(mx1, __shfl_xor_sync(0xffffffffu, mx1, 1));
        mx1 = fmaxf(mx1, __shfl_xor_sync(0xffffffffu, mx1, 2));
        float mn0 = fmaxf(m0, mx0), mn1 = fmaxf(m1, mx1);
        float scl0 = __expf(m0 - mn0), scl1 = __expf(m1 - mn1);
        float s0 = 0.f, s1 = 0.f;
#pragma unroll
        for (int nt = 0; nt < 8; nt++) {
            sc[nt][0] = __expf(sc[nt][0] - mn0);
            sc[nt][1] = __expf(sc[nt][1] - mn0);
            sc[nt][2] = __expf(sc[nt][2] - mn1);
            sc[nt][3] = __expf(sc[nt][3] - mn1);
            s0 += sc[nt][0] + sc[nt][1];
            s1 += sc[nt][2] + sc[nt][3];
        }
        s0 += __shfl_xor_sync(0xffffffffu, s0, 1);
        s0 += __shfl_xor_sync(0xffffffffu, s0, 2);
        s1 += __shfl_xor_sync(0xffffffffu, s1, 1);
        s1 += __shfl_xor_sync(0xffffffffu, s1, 2);
        l0 = l0 * scl0 + s0;
        l1 = l1 * scl1 + s1;
#pragma unroll
        for (int dt = 0; dt < 8; dt++) {
            oacc[dt][0] *= scl0; oacc[dt][1] *= scl0;
            oacc[dt][2] *= scl1; oacc[dt][3] *= scl1;
        }
        m0 = mn0; m1 = mn1;

#pragma unroll
        for (int kc = 0; kc < 8; kc++) {
            int src0 = (g << 2) + (t >> 1);
            int src1 = src0 + 2;
            float v00 = __shfl_sync(0xffffffffu, sc[kc][0], src0);
            float v01 = __shfl_sync(0xffffffffu, sc[kc][1], src0);
            float v10 = __shfl_sync(0xffffffffu, sc[kc][2], src0);
            float v11 = __shfl_sync(0xffffffffu, sc[kc][3], src0);
            float w00 = __shfl_sync(0xffffffffu, sc[kc][0], src1);
            float w01 = __shfl_sync(0xffffffffu, sc[kc][1], src1);
            float w10 = __shfl_sync(0xffffffffu, sc[kc][2], src1);
            float w11 = __shfl_sync(0xffffffffu, sc[kc][3], src1);
            bool odd = t & 1;
            unsigned a[4];
            a[0] = f2tf(odd ? v01 : v00);
            a[1] = f2tf(odd ? v11 : v10);
            a[2] = f2tf(odd ? w01 : w00);
            a[3] = f2tf(odd ? w11 : w10);
#pragma unroll
            for (int dt = 0; dt < 8; dt++) {
                int vb = (kc * 8 + t) * VS_LD + dt * 8 + g;
                unsigned bh0 = __float_as_uint(Vhi[vb]);
                unsigned bh1 = __float_as_uint(Vhi[vb + 4 * VS_LD]);
                mma_tf32(oacc[dt], a, bh0, bh1);
            }
        }
    }

    float il0 = 1.0f / l0, il1 = 1.0f / l1;
    size_t r0 = ((size_t)(b * N + q0 + g)) * HD + h * DH;
    size_t r1 = ((size_t)(b * N + q0 + 8 + g)) * HD + h * DH;
#pragma unroll
    for (int dt = 0; dt < 8; dt++) {
        int col = dt * 8 + 2 * t;
        float2 o0 = { oacc[dt][0] * il0, oacc[dt][1] * il0 };
        float2 o1 = { oacc[dt][2] * il1, oacc[dt][3] * il1 };
        *(float2*)(O + r0 + col) = o0;
        *(float2*)(O + r1 + col) = o1;
    }
}

// ------------- mask output ---------------------------------------------------
__global__ void mask_kernel(const int* __restrict__ lengths, float* __restrict__ out)
{
    int i = blockIdx.x * blockDim.x + threadIdx.x;
    int b = i / N, n = i % N;
    out[i] = (n < lengths[b]) ? 1.0f : 0.0f;
}

// -----------------------------------------------------------------------------
static const int ATTN_SMEM = (2 * 64 * KS_LD + 64 * VS_LD) * 4; // 53248 B

extern "C" void kernel_launch(void* const* d_in, const int* in_sizes, int n_in,
                              void* d_out, int out_size)
{
    const float* patches    = (const float*)d_in[0];
    const float* pe_ln1_g   = (const float*)d_in[1];
    const float* pe_W       = (const float*)d_in[2];
    const float* pe_b       = (const float*)d_in[3];
    const float* pe_ln2_g   = (const float*)d_in[4];
    const float* attn_ln_g  = (const float*)d_in[5];
    const float* qn_g       = (const float*)d_in[6];
    const float* kn_g       = (const float*)d_in[7];
    const float* Wq         = (const float*)d_in[8];
    const float* Wkv        = (const float*)d_in[9];
    const float* Wo         = (const float*)d_in[10];
    const float* ff_ln_g    = (const float*)d_in[11];
    const float* W1         = (const float*)d_in[12];
    const float* b1         = (const float*)d_in[13];
    const float* W2         = (const float*)d_in[14];
    const float* b2         = (const float*)d_in[15];
    const float* final_ln_g = (const float*)d_in[16];
    const int*   h_idx      = (const int*)d_in[17];
    const int*   w_idx      = (const int*)d_in[18];
    const int*   lengths    = (const int*)d_in[19];
    float* out = (float*)d_out;

    cudaFuncSetAttribute(attn_mma, cudaFuncAttributeMaxDynamicSharedMemorySize, ATTN_SMEM);

    float *x, *qlin, *kv, *Qb, *Kb, *Vb, *att, *hb;
    float2* st;
    cudaGetSymbolAddress((void**)&x, g_x);
    cudaGetSymbolAddress((void**)&qlin, g_qlin);
    cudaGetSymbolAddress((void**)&kv, g_kv);
    cudaGetSymbolAddress((void**)&Qb, g_Q);
    cudaGetSymbolAddress((void**)&Kb, g_K);
    cudaGetSymbolAddress((void**)&Vb, g_V);
    cudaGetSymbolAddress((void**)&att, g_att);
    cudaGetSymbolAddress((void**)&hb, g_h);
    cudaGetSymbolAddress((void**)&st, g_st);

    dim3 gDIM(DIM / 128, M / 128);
    dim3 gKV(2 * HD / 128, M / 128);
    dim3 gMLP(MLP / 128, M / 128);

    // patch embedding: LN (fused) -> Linear+bias -> LN
    ln_stats<<<M / 8, 256>>>(patches, st);
    gemm_mma<<<gDIM, 256>>>(patches, st, pe_ln1_g, pe_W, pe_b, nullptr, x, DIM, DIM, 1);
    ln_kernel<<<M / 8, 256>>>(x, pe_ln2_g, x);

    for (int i = 0; i < L; i++) {
        const float* Wq_i  = Wq  + (size_t)i * DIM * HD;
        const float* Wkv_i = Wkv + (size_t)i * DIM * 2 * HD;
        const float* Wo_i  = Wo  + (size_t)i * HD * DIM;
        const float* W1_i  = W1  + (size_t)i * DIM * MLP;
        const float* W2_i  = W2  + (size_t)i * MLP * DIM;

        ln_stats<<<M / 8, 256>>>(x, st);
        gemm_mma<<<gDIM, 256>>>(x, st, attn_ln_g + i * DIM, Wq_i, nullptr, nullptr, qlin, DIM, HD, 0);
        gemm_mma<<<gKV, 256>>>(x, st, attn_ln_g + i * DIM, Wkv_i, nullptr, nullptr, kv, DIM, 2 * HD, 0);
        qkv_prep<<<(B * H * N) / 8, 256>>>(qlin, kv, qn_g + i * H * DH, kn_g + i * H * DH,
                                           h_idx, w_idx, Qb, Kb, Vb);
        attn_mma<<<dim3(N / 64, B * H), 128, ATTN_SMEM>>>(Qb, Kb, Vb, lengths, att);
        gemm_mma<<<gDIM, 256>>>(att, nullptr, nullptr, Wo_i, nullptr, x, x, HD, DIM, 4);
        ln_stats<<<M / 8, 256>>>(x, st);
        gemm_mma<<<gMLP, 256>>>(x, st, ff_ln_g + i * DIM, W1_i, b1 + i * MLP, nullptr, hb, DIM, MLP, 3);
        gemm_mma<<<gDIM, 256>>>(hb, nullptr, nullptr, W2_i, b2 + i * DIM, x, x, MLP, DIM, 5);
    }

    ln_kernel<<<M / 8, 256>>>(x, final_ln_g, out);
    if (out_size >= M * DIM + B * N) {
        mask_kernel<<<(B * N) / 256, 256>>>(lengths, out + (size_t)M * DIM);
    }
}

// round 17
// speedup vs baseline: 2.1829x; 1.2424x over previous
#include <cuda_runtime.h>
#include <cuda_fp16.h>
#include <math.h>
#include <stdint.h>

static constexpr int B = 4, N = 2048, DIM = 768, H = 12, DH = 64, MLP = 3072, L = 2;
static constexpr int M = B * N;            // 8192 rows
static constexpr int HD = H * DH;          // 768

// ---------------- scratch (device globals; no allocation allowed) -------------
__device__ float  g_x   [M * DIM];
__device__ float  g_qlin[M * HD];
__device__ float  g_kv  [M * 2 * HD];
__device__ float  g_Q   [B * H * N * DH];
__device__ float  g_K   [B * H * N * DH];
__device__ float  g_V   [B * H * N * DH];
__device__ float  g_att [M * HD];
__device__ float  g_h   [M * MLP];
__device__ float2 g_st  [M];               // per-row LN stats (mean, rstd)

// ---------------- helpers ------------------------------------------------------
__device__ __forceinline__ void mma_f16(float* c, const unsigned* a, unsigned b0, unsigned b1) {
    asm volatile("mma.sync.aligned.m16n8k16.row.col.f32.f16.f16.f32 "
                 "{%0,%1,%2,%3}, {%4,%5,%6,%7}, {%8,%9}, {%0,%1,%2,%3};"
                 : "+f"(c[0]), "+f"(c[1]), "+f"(c[2]), "+f"(c[3])
                 : "r"(a[0]), "r"(a[1]), "r"(a[2]), "r"(a[3]), "r"(b0), "r"(b1));
}

__device__ __forceinline__ unsigned pack_h2(float lo, float hi) {
    __half2 h = __floats2half2_rn(lo, hi);
    return *(unsigned*)&h;
}

// split x,y into fp16 hi pair + fp16 residual pair
__device__ __forceinline__ void split_h2(float x, float y, unsigned& hi, unsigned& lo) {
    __half hx = __float2half_rn(x), hy = __float2half_rn(y);
    __half2 hp; hp.x = hx; hp.y = hy;
    hi = *(unsigned*)&hp;
    lo = pack_h2(x - __half2float(hx), y - __half2float(hy));
}

// ---------------- LayerNorm: full apply (warp/row) ----------------------------
__global__ void ln_kernel(const float* __restrict__ in, const float* __restrict__ g,
                          float* __restrict__ out)
{
    int warp = (blockIdx.x * blockDim.x + threadIdx.x) >> 5;
    int lane = threadIdx.x & 31;
    const float* x = in + (size_t)warp * DIM;
    float4 v[6];
    float s = 0.f;
#pragma unroll
    for (int i = 0; i < 6; i++) {
        v[i] = *(const float4*)(x + i * 128 + lane * 4);
        s += v[i].x + v[i].y + v[i].z + v[i].w;
    }
#pragma unroll
    for (int o = 16; o; o >>= 1) s += __shfl_xor_sync(0xffffffffu, s, o);
    float mean = s * (1.0f / DIM);
    float s2 = 0.f;
#pragma unroll
    for (int i = 0; i < 6; i++) {
        float a = v[i].x - mean, b = v[i].y - mean, c = v[i].z - mean, d = v[i].w - mean;
        s2 += a * a + b * b + c * c + d * d;
    }
#pragma unroll
    for (int o = 16; o; o >>= 1) s2 += __shfl_xor_sync(0xffffffffu, s2, o);
    float inv = rsqrtf(s2 * (1.0f / DIM) + 1e-5f);
    float* y = out + (size_t)warp * DIM;
#pragma unroll
    for (int i = 0; i < 6; i++) {
        float4 gg = *(const float4*)(g + i * 128 + lane * 4);
        float4 o4;
        o4.x = (v[i].x - mean) * inv * gg.x;
        o4.y = (v[i].y - mean) * inv * gg.y;
        o4.z = (v[i].z - mean) * inv * gg.z;
        o4.w = (v[i].w - mean) * inv * gg.w;
        *(float4*)(y + i * 128 + lane * 4) = o4;
    }
}

// ---------------- LayerNorm stats only (warp/row) -----------------------------
__global__ void ln_stats(const float* __restrict__ in, float2* __restrict__ st)
{
    int warp = (blockIdx.x * blockDim.x + threadIdx.x) >> 5;
    int lane = threadIdx.x & 31;
    const float* x = in + (size_t)warp * DIM;
    float4 v[6];
    float s = 0.f;
#pragma unroll
    for (int i = 0; i < 6; i++) {
        v[i] = *(const float4*)(x + i * 128 + lane * 4);
        s += v[i].x + v[i].y + v[i].z + v[i].w;
    }
#pragma unroll
    for (int o = 16; o; o >>= 1) s += __shfl_xor_sync(0xffffffffu, s, o);
    float mean = s * (1.0f / DIM);
    float s2 = 0.f;
#pragma unroll
    for (int i = 0; i < 6; i++) {
        float a = v[i].x - mean, b = v[i].y - mean, c = v[i].z - mean, d = v[i].w - mean;
        s2 += a * a + b * b + c * c + d * d;
    }
#pragma unroll
    for (int o = 16; o; o >>= 1) s2 += __shfl_xor_sync(0xffffffffu, s2, o);
    float inv = rsqrtf(s2 * (1.0f / DIM) + 1e-5f);
    if (lane == 0) { float2 r = { mean, inv }; st[warp] = r; }
}

// ---------------- fp16 GEMM, register-pipelined half2 smem --------------------
// C[M,Nc] = LN?(A)[M,K] @ W[K,Nc]; mode bit0:+bias, bit1:gelu, bit2:+res
#define A_LD2 20    // half2 per A row (16 data + 4 pad)
#define B_LD2 136   // half2 per B k2-row (128 data + 8 pad)

__device__ __forceinline__ float gelu_f(float v) {
    return 0.5f * v * (1.0f + erff(v * 0.70710678118654752f));
}

__global__ __launch_bounds__(256, 2)
void gemm_mma(const float* __restrict__ A, const float2* __restrict__ lnst,
              const float* __restrict__ lngam, const float* __restrict__ W,
              const float* __restrict__ bias, const float* __restrict__ res,
              float* __restrict__ C, int K_, int Nc, int mode)
{
    __shared__ unsigned Ah[2][128 * A_LD2];
    __shared__ unsigned Bh[2][16 * B_LD2];

    int t = threadIdx.x;
    int warp = t >> 5, lane = t & 31;
    int group = lane >> 2, tid = lane & 3;
    int wm = warp >> 1, wn = warp & 1;
    int wr = wm * 32, wc = wn * 64;
    int m0 = blockIdx.y * 128, n0 = blockIdx.x * 128;

    int ar0 = t >> 3, ak = (t & 7) * 4;
    int bk0 = t >> 5, bn = (t & 31) * 4;

    float acc[2][8][4];
#pragma unroll
    for (int a = 0; a < 2; a++)
#pragma unroll
        for (int b = 0; b < 8; b++)
#pragma unroll
            for (int c = 0; c < 4; c++) acc[a][b][c] = 0.f;

    const float* Arow = A + (size_t)m0 * K_;
    float4 ra[4], rbe[2], rbo[2];

    auto ldregs = [&](int k0) {
#pragma unroll
        for (int i = 0; i < 4; i++)
            ra[i] = *(const float4*)(Arow + (size_t)(ar0 + i * 32) * K_ + k0 + ak);
#pragma unroll
        for (int i = 0; i < 2; i++) {
            const float* p = W + (size_t)(k0 + 2 * (bk0 + i * 8)) * Nc + n0 + bn;
            rbe[i] = *(const float4*)p;
            rbo[i] = *(const float4*)(p + Nc);
        }
    };
    auto stsbuf = [&](int s, int k0) {
        float4 gg;
        if (lnst) gg = *(const float4*)(lngam + k0 + ak);
#pragma unroll
        for (int i = 0; i < 4; i++) {
            float4 v = ra[i];
            if (lnst) {
                float2 s2 = lnst[m0 + ar0 + i * 32];
                v.x = (v.x - s2.x) * s2.y * gg.x;
                v.y = (v.y - s2.x) * s2.y * gg.y;
                v.z = (v.z - s2.x) * s2.y * gg.z;
                v.w = (v.w - s2.x) * s2.y * gg.w;
            }
            uint2 u = { pack_h2(v.x, v.y), pack_h2(v.z, v.w) };
            *(uint2*)&Ah[s][(ar0 + i * 32) * A_LD2 + (ak >> 1)] = u;
        }
#pragma unroll
        for (int i = 0; i < 2; i++) {
            uint4 u = { pack_h2(rbe[i].x, rbo[i].x), pack_h2(rbe[i].y, rbo[i].y),
                        pack_h2(rbe[i].z, rbo[i].z), pack_h2(rbe[i].w, rbo[i].w) };
            *(uint4*)&Bh[s][(bk0 + i * 8) * B_LD2 + bn] = u;
        }
    };

    int KT = K_ / 32;
    ldregs(0);
    stsbuf(0, 0);
    __syncthreads();

    for (int kt = 0; kt < KT; kt++) {
        if (kt + 1 < KT) ldregs((kt + 1) * 32);
        const unsigned* As = Ah[kt & 1];
        const unsigned* Bs = Bh[kt & 1];
#pragma unroll
        for (int kk = 0; kk < 2; kk++) {
            int kb = kk * 8;
            unsigned a[2][4];
#pragma unroll
            for (int mt = 0; mt < 2; mt++) {
                int r0 = wr + mt * 16;
                a[mt][0] = As[(r0 + group) * A_LD2 + kb + tid];
                a[mt][1] = As[(r0 + 8 + group) * A_LD2 + kb + tid];
                a[mt][2] = As[(r0 + group) * A_LD2 + kb + tid + 4];
                a[mt][3] = As[(r0 + 8 + group) * A_LD2 + kb + tid + 4];
            }
#pragma unroll
            for (int nt = 0; nt < 8; nt++) {
                int col = wc + nt * 8 + group;
                unsigned b0 = Bs[(kb + tid) * B_LD2 + col];
                unsigned b1 = Bs[(kb + tid + 4) * B_LD2 + col];
                mma_f16(acc[0][nt], a[0], b0, b1);
                mma_f16(acc[1][nt], a[1], b0, b1);
            }
        }
        if (kt + 1 < KT) stsbuf((kt + 1) & 1, (kt + 1) * 32);
        __syncthreads();
    }

#pragma unroll
    for (int mt = 0; mt < 2; mt++) {
#pragma unroll
        for (int half = 0; half < 2; half++) {
            int r = m0 + wr + mt * 16 + half * 8 + group;
#pragma unroll
            for (int nt = 0; nt < 8; nt++) {
                int c = n0 + wc + nt * 8 + tid * 2;
                float v0 = acc[mt][nt][half * 2 + 0];
                float v1 = acc[mt][nt][half * 2 + 1];
                if (mode & 1) { v0 += bias[c]; v1 += bias[c + 1]; }
                if (mode & 2) { v0 = gelu_f(v0); v1 = gelu_f(v1); }
                if (mode & 4) {
                    float2 rr = *(const float2*)(res + (size_t)r * Nc + c);
                    v0 += rr.x; v1 += rr.y;
                }
                float2 o = { v0, v1 };
                *(float2*)(C + (size_t)r * Nc + c) = o;
            }
        }
    }
}

// ------------- QK rmsnorm + 2D RoPE + V transpose; 1 warp per (b,h,n) --------
__global__ void qkv_prep(const float* __restrict__ qlin, const float* __restrict__ kv,
                         const float* __restrict__ qg, const float* __restrict__ kg,
                         const int* __restrict__ hidx, const int* __restrict__ widx,
                         float* __restrict__ Q, float* __restrict__ K, float* __restrict__ V)
{
    int warp = (blockIdx.x * blockDim.x + threadIdx.x) >> 5;
    int lane = threadIdx.x & 31;
    int n = warp % N;
    int bh = warp / N;
    int h = bh % H, b = bh / H;

    size_t qsrc = ((size_t)(b * N + n)) * HD + h * DH;
    size_t kvsrc = ((size_t)(b * N + n)) * (2 * HD) + h * DH;
    float q0 = qlin[qsrc + lane], q1 = qlin[qsrc + lane + 32];
    float k0 = kv[kvsrc + lane], k1 = kv[kvsrc + lane + 32];
    float v0 = kv[kvsrc + HD + lane], v1 = kv[kvsrc + HD + lane + 32];

    float qs = q0 * q0 + q1 * q1;
    float ks = k0 * k0 + k1 * k1;
    for (int o = 16; o; o >>= 1) {
        qs += __shfl_xor_sync(0xffffffffu, qs, o);
        ks += __shfl_xor_sync(0xffffffffu, ks, o);
    }
    float rq = 8.0f / fmaxf(sqrtf(qs), 1e-12f);
    float rk = 8.0f / fmaxf(sqrtf(ks), 1e-12f);
    q0 = q0 * rq * qg[h * DH + lane];  q1 = q1 * rq * qg[h * DH + lane + 32];
    k0 = k0 * rk * kg[h * DH + lane];  k1 = k1 * rk * kg[h * DH + lane + 32];

    int hv = hidx[b * N + n], wv = widx[b * N + n];
    int fi = lane & 15;
    float invf = __expf(-(float)fi * (9.210340371976184f / 16.0f));
    float th_h = (float)hv * invf, th_w = (float)wv * invf;
    float sh, chv, sw, cw;
    __sincosf(th_h, &sh, &chv);
    __sincosf(th_w, &sw, &cw);
    float sgn = (lane < 16) ? -1.0f : 1.0f;
    float qp0 = __shfl_xor_sync(0xffffffffu, q0, 16);
    float qp1 = __shfl_xor_sync(0xffffffffu, q1, 16);
    float kp0 = __shfl_xor_sync(0xffffffffu, k0, 16);
    float kp1 = __shfl_xor_sync(0xffffffffu, k1, 16);
    q0 = q0 * chv + sgn * qp0 * sh;
    q1 = q1 * cw + sgn * qp1 * sw;
    k0 = k0 * chv + sgn * kp0 * sh;
    k1 = k1 * cw + sgn * kp1 * sw;

    size_t dst = ((size_t)bh * N + n) * DH;
    Q[dst + lane] = q0; Q[dst + lane + 32] = q1;
    K[dst + lane] = k0; K[dst + lane + 32] = k1;
    V[dst + lane] = v0; V[dst + lane + 32] = v1;
}

// ------------- attention: f16-k16 flash; QK hi/lo split, PV shuffle-free -----
#define KLD2 36   // half2 per K row: 32 dim-pairs + 4 pad (load bank g*4+t)
#define VLD2 72   // half2 per V keypair row: 64 dims + 8 pad (load bank t*8+g)

__global__ __launch_bounds__(128, 2)
void attn_mma(const float* __restrict__ Q, const float* __restrict__ K,
              const float* __restrict__ V, const int* __restrict__ lengths,
              float* __restrict__ O)
{
    __shared__ unsigned Kh2[64 * KLD2];   // [key][dim2] fp16 hi pairs
    __shared__ unsigned Kl2[64 * KLD2];   // fp16 residual pairs
    __shared__ unsigned Vh2[32 * VLD2];   // [keypair][dim] (even key, odd key)

    int bh = blockIdx.y;
    int b = bh / H, h = bh % H;
    int warp = threadIdx.x >> 5, lane = threadIdx.x & 31;
    int g = lane >> 2, t = lane & 3;
    int q0 = blockIdx.x * 64 + warp * 16;
    int len = lengths[b];

    const float* Qb = Q + (size_t)bh * N * DH;
    const float* Kb = K + (size_t)bh * N * DH;
    const float* Vb = V + (size_t)bh * N * DH;

    // Q fragments: 4 k16 chunks, hi/lo fp16 split
    unsigned qhi[4][4], qlo[4][4];
#pragma unroll
    for (int c = 0; c < 4; c++) {
        float2 f0 = *(const float2*)(Qb + (size_t)(q0 + g)     * DH + c * 16 + 2 * t);
        float2 f1 = *(const float2*)(Qb + (size_t)(q0 + 8 + g) * DH + c * 16 + 2 * t);
        float2 f2 = *(const float2*)(Qb + (size_t)(q0 + g)     * DH + c * 16 + 2 * t + 8);
        float2 f3 = *(const float2*)(Qb + (size_t)(q0 + 8 + g) * DH + c * 16 + 2 * t + 8);
        split_h2(f0.x, f0.y, qhi[c][0], qlo[c][0]);
        split_h2(f1.x, f1.y, qhi[c][1], qlo[c][1]);
        split_h2(f2.x, f2.y, qhi[c][2], qlo[c][2]);
        split_h2(f3.x, f3.y, qhi[c][3], qlo[c][3]);
    }

    float oacc[8][4];
#pragma unroll
    for (int dt = 0; dt < 8; dt++)
#pragma unroll
        for (int i = 0; i < 4; i++) oacc[dt][i] = 0.f;
    float m0 = -1e30f, m1 = -1e30f, l0 = 0.f, l1 = 0.f;

    for (int k0 = 0; k0 < len; k0 += 64) {
        __syncthreads();
        // stage K (dim-paired hi/lo) and V (key-paired via shfl)
#pragma unroll
        for (int i = 0; i < 8; i++) {
            int idx = threadIdx.x + i * 128;
            int row = idx >> 4, c4 = (idx & 15) * 4;
            int jj = k0 + row; if (jj > N - 1) jj = N - 1;
            float4 kv4 = *(const float4*)(Kb + (size_t)jj * DH + c4);
            float4 vv4 = *(const float4*)(Vb + (size_t)jj * DH + c4);
            unsigned kh0, kl0, kh1, kl1;
            split_h2(kv4.x, kv4.y, kh0, kl0);
            split_h2(kv4.z, kv4.w, kh1, kl1);
            uint2 uh = { kh0, kh1 }, ul = { kl0, kl1 };
            *(uint2*)&Kh2[row * KLD2 + (c4 >> 1)] = uh;
            *(uint2*)&Kl2[row * KLD2 + (c4 >> 1)] = ul;
            // V: lanes 0-15 hold even key, 16-31 odd key (same dims)
            float vx = __shfl_xor_sync(0xffffffffu, vv4.x, 16);
            float vy = __shfl_xor_sync(0xffffffffu, vv4.y, 16);
            float vz = __shfl_xor_sync(0xffffffffu, vv4.z, 16);
            float vw = __shfl_xor_sync(0xffffffffu, vv4.w, 16);
            if (lane < 16) {
                uint4 u = { pack_h2(vv4.x, vx), pack_h2(vv4.y, vy),
                            pack_h2(vv4.z, vz), pack_h2(vv4.w, vw) };
                *(uint4*)&Vh2[(row >> 1) * VLD2 + c4] = u;
            }
        }
        __syncthreads();

        // S = Q K^T: 3x f16 split per k16 chunk
        float sc[8][4];
#pragma unroll
        for (int nt = 0; nt < 8; nt++)
#pragma unroll
            for (int i = 0; i < 4; i++) sc[nt][i] = 0.f;
#pragma unroll
        for (int c = 0; c < 4; c++) {
#pragma unroll
            for (int nt = 0; nt < 8; nt++) {
                int kb = (nt * 8 + g) * KLD2 + c * 8 + t;
                unsigned bh0 = Kh2[kb],     bh1 = Kh2[kb + 4];
                unsigned bl0 = Kl2[kb],     bl1 = Kl2[kb + 4];
                mma_f16(sc[nt], qhi[c], bh0, bh1);
                mma_f16(sc[nt], qhi[c], bl0, bl1);
                mma_f16(sc[nt], qlo[c], bh0, bh1);
            }
        }

        // mask + online softmax (C layout unchanged)
        float mx0 = -1e30f, mx1 = -1e30f;
#pragma unroll
        for (int nt = 0; nt < 8; nt++) {
            int j = k0 + nt * 8 + 2 * t;
            if (j >= len)     { sc[nt][0] = -1e30f; sc[nt][2] = -1e30f; }
            if (j + 1 >= len) { sc[nt][1] = -1e30f; sc[nt][3] = -1e30f; }
            mx0 = fmaxf(mx0, fmaxf(sc[nt][0], sc[nt][1]));
            mx1 = fmaxf(mx1, fmaxf(sc[nt][2], sc[nt][3]));
        }
        mx0 = fmaxf(mx0, __shfl_xor_sync(0xffffffffu, mx0, 1));
        mx0 = fmaxf(mx0, __shfl_xor_sync(0xffffffffu, mx0, 2));
        mx1 = fmaxf(mx1, __shfl_xor_sync(0xffffffffu, mx1, 1));
        mx1 = fmaxf(mx1, __shfl_xor_sync(0xffffffffu, mx1, 2));
        float mn0 = fmaxf(m0, mx0), mn1 = fmaxf(m1, mx1);
        float scl0 = __expf(m0 - mn0), scl1 = __expf(m1 - mn1);
        float s0 = 0.f, s1 = 0.f;
#pragma unroll
        for (int nt = 0; nt < 8; nt++) {
            sc[nt][0] = __expf(sc[nt][0] - mn0);
            sc[nt][1] = __expf(sc[nt][1] - mn0);
            sc[nt][2] = __expf(sc[nt][2] - mn1);
            sc[nt][3] = __expf(sc[nt][3] - mn1);
            s0 += sc[nt][0] + sc[nt][1];
            s1 += sc[nt][2] + sc[nt][3];
        }
        s0 += __shfl_xor_sync(0xffffffffu, s0, 1);
        s0 += __shfl_xor_sync(0xffffffffu, s0, 2);
        s1 += __shfl_xor_sync(0xffffffffu, s1, 1);
        s1 += __shfl_xor_sync(0xffffffffu, s1, 2);
        l0 = l0 * scl0 + s0;
        l1 = l1 * scl1 + s1;
#pragma unroll
        for (int dt = 0; dt < 8; dt++) {
            oacc[dt][0] *= scl0; oacc[dt][1] *= scl0;
            oacc[dt][2] *= scl1; oacc[dt][3] *= scl1;
        }
        m0 = mn0; m1 = mn1;

        // O += P V: f16 k16, A-frag built from own registers (no shuffles)
#pragma unroll
        for (int c = 0; c < 4; c++) {
            int kc0 = 2 * c, kc1 = 2 * c + 1;
            unsigned a[4];
            a[0] = pack_h2(sc[kc0][0], sc[kc0][1]);
            a[1] = pack_h2(sc[kc0][2], sc[kc0][3]);
            a[2] = pack_h2(sc[kc1][0], sc[kc1][1]);
            a[3] = pack_h2(sc[kc1][2], sc[kc1][3]);
#pragma unroll
            for (int dt = 0; dt < 8; dt++) {
                unsigned b0 = Vh2[(c * 8 + t) * VLD2 + dt * 8 + g];
                unsigned b1 = Vh2[(c * 8 + t + 4) * VLD2 + dt * 8 + g];
                mma_f16(oacc[dt], a, b0, b1);
            }
        }
    }

    float il0 = 1.0f / l0, il1 = 1.0f / l1;
    size_t r0 = ((size_t)(b * N + q0 + g)) * HD + h * DH;
    size_t r1 = ((size_t)(b * N + q0 + 8 + g)) * HD + h * DH;
#pragma unroll
    for (int dt = 0; dt < 8; dt++) {
        int col = dt * 8 + 2 * t;
        float2 o0 = { oacc[dt][0] * il0, oacc[dt][1] * il0 };
        float2 o1 = { oacc[dt][2] * il1, oacc[dt][3] * il1 };
        *(float2*)(O + r0 + col) = o0;
        *(float2*)(O + r1 + col) = o1;
    }
}

// ------------- mask output ---------------------------------------------------
__global__ void mask_kernel(const int* __restrict__ lengths, float* __restrict__ out)
{
    int i = blockIdx.x * blockDim.x + threadIdx.x;
    int b = i / N, n = i % N;
    out[i] = (n < lengths[b]) ? 1.0f : 0.0f;
}

// -----------------------------------------------------------------------------
extern "C" void kernel_launch(void* const* d_in, const int* in_sizes, int n_in,
                              void* d_out, int out_size)
{
    const float* patches    = (const float*)d_in[0];
    const float* pe_ln1_g   = (const float*)d_in[1];
    const float* pe_W       = (const float*)d_in[2];
    const float* pe_b       = (const float*)d_in[3];
    const float* pe_ln2_g   = (const float*)d_in[4];
    const float* attn_ln_g  = (const float*)d_in[5];
    const float* qn_g       = (const float*)d_in[6];
    const float* kn_g       = (const float*)d_in[7];
    const float* Wq         = (const float*)d_in[8];
    const float* Wkv        = (const float*)d_in[9];
    const float* Wo         = (const float*)d_in[10];
    const float* ff_ln_g    = (const float*)d_in[11];
    const float* W1         = (const float*)d_in[12];
    const float* b1         = (const float*)d_in[13];
    const float* W2         = (const float*)d_in[14];
    const float* b2         = (const float*)d_in[15];
    const float* final_ln_g = (const float*)d_in[16];
    const int*   h_idx      = (const int*)d_in[17];
    const int*   w_idx      = (const int*)d_in[18];
    const int*   lengths    = (const int*)d_in[19];
    float* out = (float*)d_out;

    float *x, *qlin, *kv, *Qb, *Kb, *Vb, *att, *hb;
    float2* st;
    cudaGetSymbolAddress((void**)&x, g_x);
    cudaGetSymbolAddress((void**)&qlin, g_qlin);
    cudaGetSymbolAddress((void**)&kv, g_kv);
    cudaGetSymbolAddress((void**)&Qb, g_Q);
    cudaGetSymbolAddress((void**)&Kb, g_K);
    cudaGetSymbolAddress((void**)&Vb, g_V);
    cudaGetSymbolAddress((void**)&att, g_att);
    cudaGetSymbolAddress((void**)&hb, g_h);
    cudaGetSymbolAddress((void**)&st, g_st);

    dim3 gDIM(DIM / 128, M / 128);
    dim3 gKV(2 * HD / 128, M / 128);
    dim3 gMLP(MLP / 128, M / 128);

    // patch embedding: LN (fused) -> Linear+bias -> LN
    ln_stats<<<M / 8, 256>>>(patches, st);
    gemm_mma<<<gDIM, 256>>>(patches, st, pe_ln1_g, pe_W, pe_b, nullptr, x, DIM, DIM, 1);
    ln_kernel<<<M / 8, 256>>>(x, pe_ln2_g, x);

    for (int i = 0; i < L; i++) {
        const float* Wq_i  = Wq  + (size_t)i * DIM * HD;
        const float* Wkv_i = Wkv + (size_t)i * DIM * 2 * HD;
        const float* Wo_i  = Wo  + (size_t)i * HD * DIM;
        const float* W1_i  = W1  + (size_t)i * DIM * MLP;
        const float* W2_i  = W2  + (size_t)i * MLP * DIM;

        ln_stats<<<M / 8, 256>>>(x, st);
        gemm_mma<<<gDIM, 256>>>(x, st, attn_ln_g + i * DIM, Wq_i, nullptr, nullptr, qlin, DIM, HD, 0);
        gemm_mma<<<gKV, 256>>>(x, st, attn_ln_g + i * DIM, Wkv_i, nullptr, nullptr, kv, DIM, 2 * HD, 0);
        qkv_prep<<<(B * H * N) / 8, 256>>>(qlin, kv, qn_g + i * H * DH, kn_g + i * H * DH,
                                           h_idx, w_idx, Qb, Kb, Vb);
        attn_mma<<<dim3(N / 64, B * H), 128>>>(Qb, Kb, Vb, lengths, att);
        gemm_mma<<<gDIM, 256>>>(att, nullptr, nullptr, Wo_i, nullptr, x, x, HD, DIM, 4);
        ln_stats<<<M / 8, 256>>>(x, st);
        gemm_mma<<<gMLP, 256>>>(x, st, ff_ln_g + i * DIM, W1_i, b1 + i * MLP, nullptr, hb, DIM, MLP, 3);
        gemm_mma<<<gDIM, 256>>>(hb, nullptr, nullptr, W2_i, b2 + i * DIM, x, x, MLP, DIM, 5);
    }

    ln_kernel<<<M / 8, 256>>>(x, final_ln_g, out);
    if (out_size >= M * DIM + B * N) {
        mask_kernel<<<(B * N) / 256, 256>>>(lengths, out + (size_t)M * DIM);
    }
}